// round 13
// baseline (speedup 1.0000x reference)
#include <cuda_runtime.h>
#include <cuda_fp16.h>
#include <cstdint>

// Problem constants
#define B_   8
#define C_   128
#define CI_  64
#define N_   4096
// P = 2^(s - SHIFT2), s = S*log2(e). SHIFT2=16: fp16 Inf only if S > 22.1 natural.
#define SHIFT2 16.0f
#define LOG2E  1.4426950408889634f

// ---------------- scratch (device globals; no allocations) ----------------
__device__ __half d_th  [B_*N_*CI_];   // theta*log2e [b][n][c]
__device__ __half d_phih[B_*N_*CI_];   // phi   [b][m][c]
__device__ __half d_g   [B_*CI_*N_];   // g     [b][c][m] (unscaled)
__device__ __half d_gih [B_*CI_*N_];   // g/Z   [b][c][m]
__device__ __half d_y   [B_*N_*CI_];   // y     [b][n][c]

// ---------------- helpers ----------------
// fp16 m16n8k16, fp32 accumulate
__device__ __forceinline__ void mmah(float* c, const unsigned* a, const unsigned* b) {
    asm volatile(
        "mma.sync.aligned.m16n8k16.row.col.f32.f16.f16.f32 "
        "{%0,%1,%2,%3},{%4,%5,%6,%7},{%8,%9},{%0,%1,%2,%3};\n"
        : "+f"(c[0]), "+f"(c[1]), "+f"(c[2]), "+f"(c[3])
        : "r"(a[0]), "r"(a[1]), "r"(a[2]), "r"(a[3]),
          "r"(b[0]), "r"(b[1]));
}

__device__ __forceinline__ void ldsm4(unsigned* r, unsigned addr) {
    asm volatile("ldmatrix.sync.aligned.m8n8.x4.shared.b16 {%0,%1,%2,%3}, [%4];"
        : "=r"(r[0]), "=r"(r[1]), "=r"(r[2]), "=r"(r[3]) : "r"(addr));
}

__device__ __forceinline__ void cpa16(void* dst_smem, const void* src) {
    unsigned d = (unsigned)__cvta_generic_to_shared(dst_smem);
    asm volatile("cp.async.cg.shared.global [%0], [%1], 16;" :: "r"(d), "l"(src));
}
#define CP_COMMIT()  asm volatile("cp.async.commit_group;")
#define CP_WAIT2()   asm volatile("cp.async.wait_group 2;")
#define CP_WAIT1()   asm volatile("cp.async.wait_group 1;")
#define CP_WAIT0()   asm volatile("cp.async.wait_group 0;")

__device__ __forceinline__ unsigned smem_u32(const void* p) {
    return (unsigned)__cvta_generic_to_shared(p);
}
// P pair = 2^(s - SHIFT2) through fp16 (identical path in k2 and k3)
__device__ __forceinline__ __half2 pexp2(float s0, float s1) {
    return h2exp2(__floats2half2_rn(s0 - SHIFT2, s1 - SHIFT2));
}

// =====================================================================
// K1: projections, now fp16 m16n8k16 (same 10-bit mantissa as tf32).
//   mtile 0: g -> d_g[c][m], 1: theta*log2e -> d_th[n][c], 2: phi -> d_phih[m][c]
// A = weights [64][K=128] fp16; B = x^T tile [128 n][128 c] fp16
// (scalar-transposed staging). grid (3, 256), block 256.
// smem: As[64][136] (17408 B) + Bs[128][136] (34816 B) = 52224 B
// =====================================================================
__global__ void __launch_bounds__(256)
k1_proj(const float* __restrict__ x,
        const float* __restrict__ g_w,  const float* __restrict__ g_b,
        const float* __restrict__ th_w, const float* __restrict__ th_b,
        const float* __restrict__ ph_w, const float* __restrict__ ph_b)
{
    extern __shared__ char smc[];
    __half* As = reinterpret_cast<__half*>(smc);           // [64][136]
    __half* Bs = reinterpret_cast<__half*>(smc + 17408);   // [128][136]

    const int tid  = threadIdx.x;
    const int warp = tid >> 5, lane = tid & 31;
    const int g = lane >> 2, q = lane & 3;
    const int wr0 = (warp >> 2) * 32;   // m: 0 or 32
    const int wc0 = (warp & 3) * 32;    // n: 0,32,64,96

    const int mtile = blockIdx.x;
    const int ntot0 = blockIdx.y * 128;
    const int b  = ntot0 >> 12;
    const int n0 = ntot0 & (N_ - 1);

    const float* wsel = (mtile == 0) ? g_w : (mtile == 1 ? th_w : ph_w);
    const float* bsel = (mtile == 0) ? g_b : (mtile == 1 ? th_b : ph_b);
    const float wscale = (mtile == 1) ? LOG2E : 1.0f;

    // stage A: weights [64][128] fp32 -> fp16, scaled
    for (int i = tid; i < 64*32; i += 256) {
        int r = i >> 5, k4 = (i & 31) * 4;
        float4 v = *reinterpret_cast<const float4*>(wsel + r*128 + k4);
        __half2 h0 = __floats2half2_rn(v.x * wscale, v.y * wscale);
        __half2 h1 = __floats2half2_rn(v.z * wscale, v.w * wscale);
        *reinterpret_cast<__half2*>(As + r*136 + k4)     = h0;
        *reinterpret_cast<__half2*>(As + r*136 + k4 + 2) = h1;
    }
    // stage B: x^T tile -> Bs[n][c] fp16 (transposed scalar stores)
    for (int i = tid; i < 128*32; i += 256) {
        int c = i >> 5, j4 = (i & 31) * 4;
        float4 v = *reinterpret_cast<const float4*>(
            x + ((size_t)b*C_ + c) * N_ + n0 + j4);
        Bs[(j4    )*136 + c] = __float2half_rn(v.x);
        Bs[(j4 + 1)*136 + c] = __float2half_rn(v.y);
        Bs[(j4 + 2)*136 + c] = __float2half_rn(v.z);
        Bs[(j4 + 3)*136 + c] = __float2half_rn(v.w);
    }
    __syncthreads();

    // per-lane ldmatrix byte offsets (row stride = 272 B)
    const unsigned offA = smem_u32(As)
        + (unsigned)((wr0 + (lane & 15)) * 272 + (lane >> 4) * 16);
    const unsigned offB = smem_u32(Bs)
        + (unsigned)((wc0 + (lane & 7) + ((lane >> 4) << 3)) * 272
                     + ((lane >> 3) & 1) * 16);

    float acc[2][4][4];
    #pragma unroll
    for (int mi = 0; mi < 2; mi++)
        #pragma unroll
        for (int ni = 0; ni < 4; ni++)
            #pragma unroll
            for (int e = 0; e < 4; e++) acc[mi][ni][e] = 0.f;

    #pragma unroll
    for (int kj = 0; kj < 8; kj++) {
        unsigned a[2][4], bb[8];
        ldsm4(a[0], offA +        kj*32);
        ldsm4(a[1], offA + 4352 + kj*32);   // +16 rows (16*272)
        ldsm4(bb,     offB +        kj*32); // ni 0,1
        ldsm4(bb + 4, offB + 4352 + kj*32); // ni 2,3
        #pragma unroll
        for (int mi = 0; mi < 2; mi++)
            #pragma unroll
            for (int ni = 0; ni < 4; ni++)
                mmah(acc[mi][ni], a[mi], bb + ni*2);
    }

    #pragma unroll
    for (int mi = 0; mi < 2; mi++) {
        #pragma unroll
        for (int ni = 0; ni < 4; ni++) {
            #pragma unroll
            for (int e = 0; e < 4; e++) {
                int row = wr0 + mi*16 + g + ((e >> 1) * 8);   // out channel 0..63
                int col = wc0 + ni*8 + 2*q + (e & 1);         // spatial
                __half h = __float2half_rn(acc[mi][ni][e] + bsel[row]*wscale);
                int nglob = n0 + col;
                if (mtile == 0)
                    d_g[((size_t)b*CI_ + row) * N_ + nglob] = h;
                else if (mtile == 1)
                    d_th[((size_t)b*N_ + nglob) * CI_ + row] = h;
                else
                    d_phih[((size_t)b*N_ + nglob) * CI_ + row] = h;
            }
        }
    }
}

// =====================================================================
// K2: Z[m] = sum_n 2^(s[n,m]-SHIFT2); writes d_gih = g/Z ([c][m]).
// 128-query chunks (32 chunks), 4-deep theta ring, prefetch depth 2,
// ONE barrier per chunk. grid (32, 8), block 256. Unchanged from R12.
// =====================================================================
__global__ void __launch_bounds__(256, 2)
k2_stats()
{
    extern __shared__ char smc[];
    __half* phi_s = reinterpret_cast<__half*>(smc);            // [128][72]    18432 B
    __half* th_s  = reinterpret_cast<__half*>(smc + 18432);    // 4 x [128][72] 73728 B
    __half* g_s   = reinterpret_cast<__half*>(smc + 92160);    // [64][136]    17408 B
    float*  red   = reinterpret_cast<float*>(smc + 109568);    // 256 floats
    float*  cinv  = reinterpret_cast<float*>(smc + 110592);    // 128 floats

    const int tid  = threadIdx.x;
    const int warp = tid >> 5, lane = tid & 31;
    const int q = lane & 3;
    const int wr = warp >> 2;               // 0..1 (query half: rows wr*64..)
    const int wc = warp & 3;                // 0..3 (key cols)

    const int b  = blockIdx.y;
    const int m0 = blockIdx.x * 128;

    // stage phi key-tile [128 keys][64 c] + g tile [64 c][128 m] + th chunks 0,1
    const __half* phb = d_phih + ((size_t)b*N_ + m0) * CI_;
    for (int i = tid; i < 1024; i += 256) {
        int r = i >> 3, ch = (i & 7) * 8;
        cpa16(phi_s + r*72 + ch, phb + (size_t)r*CI_ + ch);
    }
    const __half* gsrc = d_g + (size_t)b*CI_*N_ + m0;
    for (int i = tid; i < 1024; i += 256) {
        int c = i >> 4, ch = (i & 15) * 8;
        cpa16(g_s + c*136 + ch, gsrc + (size_t)c*N_ + ch);
    }
    const __half* thb = d_th + (size_t)b*N_*CI_;
    for (int i = tid; i < 1024; i += 256) {
        int r = i >> 3, ch = (i & 7) * 8;
        cpa16(th_s + r*72 + ch, thb + (size_t)r*CI_ + ch);
    }
    CP_COMMIT();
    for (int i = tid; i < 1024; i += 256) {
        int r = i >> 3, ch = (i & 7) * 8;
        cpa16(th_s + 128*72 + r*72 + ch, thb + (size_t)(128 + r)*CI_ + ch);
    }
    CP_COMMIT();

    // per-lane ldmatrix byte offsets (row stride = 144 B)
    const unsigned offA = (unsigned)((wr*64 + (lane & 15)) * 144 + (lane >> 4) * 16);
    const unsigned offB = (unsigned)((wc*32 + (lane & 7) + (lane >> 4) * 8) * 144
                                     + ((lane >> 3) & 1) * 16);
    const unsigned phiB = smem_u32(phi_s) + offB;

    float zpart[8];
    #pragma unroll
    for (int i = 0; i < 8; i++) zpart[i] = 0.f;

    for (int ns = 0; ns < 32; ns++) {
        if (ns + 2 < 32) {
            __half* dst = th_s + ((ns + 2) & 3) * (128*72);
            const __half* src = thb + (size_t)(ns + 2)*128*CI_;
            for (int i = tid; i < 1024; i += 256) {
                int r = i >> 3, ch = (i & 7) * 8;
                cpa16(dst + r*72 + ch, src + (size_t)r*CI_ + ch);
            }
            CP_COMMIT();
            CP_WAIT2();
        } else if (ns + 1 < 32) {
            CP_WAIT1();
        } else {
            CP_WAIT0();
        }
        __syncthreads();   // single barrier per chunk (safe: 4-deep ring)
        const unsigned thA = smem_u32(th_s) + (unsigned)((ns & 3) * (128*72*2)) + offA;

        float acc[4][4][4];
        #pragma unroll
        for (int mi = 0; mi < 4; mi++)
            #pragma unroll
            for (int ni = 0; ni < 4; ni++)
                #pragma unroll
                for (int e = 0; e < 4; e++) acc[mi][ni][e] = 0.f;

        #pragma unroll
        for (int kj = 0; kj < 4; kj++) {
            unsigned bb[8];
            ldsm4(bb,     phiB + kj*32);          // ni 0,1
            ldsm4(bb + 4, phiB + 2304 + kj*32);   // ni 2,3
            #pragma unroll
            for (int mi = 0; mi < 4; mi++) {
                unsigned a[4];
                ldsm4(a, thA + mi*2304 + kj*32);  // 16 rows per mi (16*144=2304)
                #pragma unroll
                for (int ni = 0; ni < 4; ni++)
                    mmah(acc[mi][ni], a, bb + ni*2);
            }
        }

        // exp + Z partials
        #pragma unroll
        for (int ni = 0; ni < 4; ni++) {
            #pragma unroll
            for (int mi = 0; mi < 4; mi++) {
                float2 e0 = __half22float2(pexp2(acc[mi][ni][0], acc[mi][ni][1]));
                float2 e1 = __half22float2(pexp2(acc[mi][ni][2], acc[mi][ni][3]));
                zpart[ni*2    ] += e0.x + e1.x;
                zpart[ni*2 + 1] += e0.y + e1.y;
            }
        }
    }

    // reduce over g-lanes (xor 4, 8, 16)
    #pragma unroll
    for (int i = 0; i < 8; i++) {
        #pragma unroll
        for (int o = 4; o < 32; o <<= 1)
            zpart[i] += __shfl_xor_sync(0xffffffffu, zpart[i], o);
    }
    __syncthreads();
    if ((lane >> 2) == 0) {
        #pragma unroll
        for (int ni = 0; ni < 4; ni++)
            #pragma unroll
            for (int jj = 0; jj < 2; jj++)
                red[wr*128 + wc*32 + ni*8 + 2*q + jj] = zpart[ni*2 + jj];
    }
    __syncthreads();
    if (tid < 128) cinv[tid] = 1.0f / (red[tid] + red[128 + tid]);
    __syncthreads();

    // write g' = g * cinv to d_gih [c][m] (half2 along m, coalesced)
    for (int i = tid; i < 64*64; i += 256) {
        int c = i >> 6, mp = i & 63;
        __half2 gv = *reinterpret_cast<__half2*>(g_s + c*136 + 2*mp);
        float2 gf = __half22float2(gv);
        __half2 o = __floats2half2_rn(gf.x * cinv[2*mp], gf.y * cinv[2*mp + 1]);
        *reinterpret_cast<__half2*>(d_gih + ((size_t)b*CI_ + c) * N_ + m0 + 2*mp) = o;
    }
}

// =====================================================================
// K3: y = 2^(s-SHIFT2) @ g' (recompute). 4-deep ring, prefetch depth 2,
// ONE barrier per chunk. grid (32, 8), block 256. Unchanged from R12.
// =====================================================================
__global__ void __launch_bounds__(256, 2)
k3_attn()
{
    extern __shared__ char smc[];
    __half* phi_s = reinterpret_cast<__half*>(smc);            // 4 x [64][72]
    __half* gi_s  = reinterpret_cast<__half*>(smc + 36864);    // 4 x [64][72]

    const int tid  = threadIdx.x;
    const int warp = tid >> 5, lane = tid & 31;
    const int g = lane >> 2, q = lane & 3;
    const int rb = warp * 16;

    const int b  = blockIdx.y;
    const int n0 = blockIdx.x * 128;

    // hoist theta A-fragments (warp's 16 query rows, k=64 -> 4 chunks)
    unsigned a_th[4][4];
    {
        const __half* tb = d_th + ((size_t)b*N_ + n0 + rb) * CI_;
        #pragma unroll
        for (int kj = 0; kj < 4; kj++) {
            const __half* pc = tb + 16*kj + 2*q;
            a_th[kj][0] = *reinterpret_cast<const unsigned*>(pc + (size_t)g*CI_);
            a_th[kj][1] = *reinterpret_cast<const unsigned*>(pc + (size_t)(g+8)*CI_);
            a_th[kj][2] = *reinterpret_cast<const unsigned*>(pc + (size_t)g*CI_ + 8);
            a_th[kj][3] = *reinterpret_cast<const unsigned*>(pc + (size_t)(g+8)*CI_ + 8);
        }
    }

    // per-lane ldmatrix byte offset for B tiles (row stride 144 B)
    const unsigned offB = (unsigned)(((lane & 7) + (lane >> 4) * 8) * 144
                                     + ((lane >> 3) & 1) * 16);

    float yacc[8][4];
    #pragma unroll
    for (int ni = 0; ni < 8; ni++)
        #pragma unroll
        for (int e = 0; e < 4; e++) yacc[ni][e] = 0.f;

    const __half* phb = d_phih + (size_t)b*N_*CI_;
    const __half* gib = d_gih + (size_t)b*CI_*N_;

    // prologue: stage chunks 0 and 1 (separate commit groups)
    #pragma unroll
    for (int pc = 0; pc < 2; pc++) {
        __half* pd = phi_s + pc * (64*72);
        __half* gd = gi_s  + pc * (64*72);
        const int mm = pc * 64;
        for (int i = tid; i < 512; i += 256) {
            int r = i >> 3, ch = (i & 7) * 8;
            cpa16(pd + r*72 + ch, phb + (size_t)(mm + r)*CI_ + ch);
            cpa16(gd + r*72 + ch, gib + (size_t)r*N_ + mm + ch);
        }
        CP_COMMIT();
    }

    for (int ms = 0; ms < 64; ms++) {
        if (ms + 2 < 64) {
            const int m2 = (ms + 2) * 64;
            __half* pd = phi_s + ((ms + 2) & 3) * (64*72);
            __half* gd = gi_s  + ((ms + 2) & 3) * (64*72);
            for (int i = tid; i < 512; i += 256) {
                int r = i >> 3, ch = (i & 7) * 8;
                cpa16(pd + r*72 + ch, phb + (size_t)(m2 + r)*CI_ + ch);
                cpa16(gd + r*72 + ch, gib + (size_t)r*N_ + m2 + ch);
            }
            CP_COMMIT();
            CP_WAIT2();
        } else if (ms + 1 < 64) {
            CP_WAIT1();
        } else {
            CP_WAIT0();
        }
        __syncthreads();   // single barrier per chunk (safe: 4-deep ring)
        const unsigned pB = smem_u32(phi_s) + (unsigned)((ms & 3) * (64*72*2)) + offB;
        const unsigned gB = smem_u32(gi_s)  + (unsigned)((ms & 3) * (64*72*2)) + offB;

        // GEMM1: S tile 16x64 per warp
        float acc[8][4];
        #pragma unroll
        for (int ni = 0; ni < 8; ni++)
            #pragma unroll
            for (int e = 0; e < 4; e++) acc[ni][e] = 0.f;

        #pragma unroll
        for (int kj = 0; kj < 4; kj++) {
            unsigned bb[16];
            ldsm4(bb,      pB +        kj*32);   // ni 0,1
            ldsm4(bb + 4,  pB + 2304 + kj*32);   // ni 2,3
            ldsm4(bb + 8,  pB + 4608 + kj*32);   // ni 4,5
            ldsm4(bb + 12, pB + 6912 + kj*32);   // ni 6,7
            #pragma unroll
            for (int ni = 0; ni < 8; ni++)
                mmah(acc[ni], a_th[kj], bb + ni*2);
        }

        // P = 2^(S - SHIFT2) -> fp16 A-frags directly
        unsigned pA[8][2];
        #pragma unroll
        for (int ni = 0; ni < 8; ni++) {
            __half2 h0 = pexp2(acc[ni][0], acc[ni][1]);
            __half2 h1 = pexp2(acc[ni][2], acc[ni][3]);
            pA[ni][0] = *reinterpret_cast<unsigned*>(&h0);
            pA[ni][1] = *reinterpret_cast<unsigned*>(&h1);
        }

        // GEMM2: Y += P @ g'
        #pragma unroll
        for (int j = 0; j < 4; j++) {
            unsigned A[4] = { pA[2*j][0], pA[2*j][1], pA[2*j+1][0], pA[2*j+1][1] };
            unsigned bb[16];
            ldsm4(bb,      gB +        j*32);
            ldsm4(bb + 4,  gB + 2304 + j*32);
            ldsm4(bb + 8,  gB + 4608 + j*32);
            ldsm4(bb + 12, gB + 6912 + j*32);
            #pragma unroll
            for (int ni = 0; ni < 8; ni++)
                mmah(yacc[ni], A, bb + ni*2);
        }
    }

    // write Y (fp16, half2 pairs along c)
    #pragma unroll
    for (int ni = 0; ni < 8; ni++) {
        int row = n0 + rb + g;
        __half* base0 = d_y + ((size_t)b*N_ + row) * CI_ + ni*8 + 2*q;
        __half* base1 = d_y + ((size_t)b*N_ + row + 8) * CI_ + ni*8 + 2*q;
        *reinterpret_cast<__half2*>(base0) = __floats2half2_rn(yacc[ni][0], yacc[ni][1]);
        *reinterpret_cast<__half2*>(base1) = __floats2half2_rn(yacc[ni][2], yacc[ni][3]);
    }
}

// =====================================================================
// K4 (fp16 mma): out = W_w @ y^T + W_b + x. Unchanged.
// grid (2, 32, 8), block 256.
// =====================================================================
__global__ void __launch_bounds__(256, 3)
k4_out(const float* __restrict__ x,
       const float* __restrict__ Ww, const float* __restrict__ Wb,
       float* __restrict__ out)
{
    extern __shared__ char smc[];
    __half* Ws = reinterpret_cast<__half*>(smc);           // 64 x 72
    __half* Ys = reinterpret_cast<__half*>(smc + 9216);    // 128 x 72

    const int tid  = threadIdx.x;
    const int warp = tid >> 5, lane = tid & 31;
    const int g = lane >> 2, q = lane & 3;
    const int wr0 = (warp >> 2) * 32;
    const int wc0 = (warp & 3) * 32;

    const int co0 = blockIdx.x * 64;
    const int n0  = blockIdx.y * 128;
    const int b   = blockIdx.z;

    for (int i = tid; i < 1024; i += 256) {
        int r = i >> 3, ch = (i & 7) * 8;
        cpa16(Ys + r*72 + ch, d_y + ((size_t)b*N_ + n0 + r)*CI_ + ch);
    }
    CP_COMMIT();
    for (int i = tid; i < 64*16; i += 256) {
        int r = i >> 4, c4 = (i & 15) * 4;
        float4 v = *reinterpret_cast<const float4*>(Ww + (co0 + r)*CI_ + c4);
        __half2 h0 = __floats2half2_rn(v.x, v.y);
        __half2 h1 = __floats2half2_rn(v.z, v.w);
        *reinterpret_cast<__half2*>(Ws + r*72 + c4)     = h0;
        *reinterpret_cast<__half2*>(Ws + r*72 + c4 + 2) = h1;
    }
    CP_WAIT0();
    __syncthreads();

    float acc[2][4][4];
    #pragma unroll
    for (int mi = 0; mi < 2; mi++)
        #pragma unroll
        for (int ni = 0; ni < 4; ni++)
            #pragma unroll
            for (int e = 0; e < 4; e++) acc[mi][ni][e] = 0.f;

    #pragma unroll
    for (int kj = 0; kj < 4; kj++) {
        unsigned a[2][4], bb[4][2];
        #pragma unroll
        for (int mi = 0; mi < 2; mi++) {
            int r0 = wr0 + mi*16 + g;
            const __half* pr = Ws + 16*kj + 2*q;
            a[mi][0] = *reinterpret_cast<const unsigned*>(pr + (size_t)r0*72);
            a[mi][1] = *reinterpret_cast<const unsigned*>(pr + (size_t)(r0+8)*72);
            a[mi][2] = *reinterpret_cast<const unsigned*>(pr + (size_t)r0*72 + 8);
            a[mi][3] = *reinterpret_cast<const unsigned*>(pr + (size_t)(r0+8)*72 + 8);
        }
        #pragma unroll
        for (int ni = 0; ni < 4; ni++) {
            int col = wc0 + ni*8 + g;
            const __half* pc = Ys + (size_t)col*72 + 16*kj + 2*q;
            bb[ni][0] = *reinterpret_cast<const unsigned*>(pc);
            bb[ni][1] = *reinterpret_cast<const unsigned*>(pc + 8);
        }
        #pragma unroll
        for (int mi = 0; mi < 2; mi++)
            #pragma unroll
            for (int ni = 0; ni < 4; ni++)
                mmah(acc[mi][ni], a[mi], bb[ni]);
    }

    #pragma unroll
    for (int mi = 0; mi < 2; mi++) {
        #pragma unroll
        for (int ni = 0; ni < 4; ni++) {
            #pragma unroll
            for (int ep = 0; ep < 2; ep++) {
                int row = co0 + wr0 + mi*16 + g + ep*8;
                int col = n0 + wc0 + ni*8 + 2*q;
                size_t o = ((size_t)b*C_ + row) * N_ + col;
                float wb = Wb[row];
                float2 xv = *reinterpret_cast<const float2*>(x + o);
                float2 ov;
                ov.x = acc[mi][ni][ep*2    ] + wb + xv.x;
                ov.y = acc[mi][ni][ep*2 + 1] + wb + xv.y;
                *reinterpret_cast<float2*>(out + o) = ov;
            }
        }
    }
}

// =====================================================================
extern "C" void kernel_launch(void* const* d_in, const int* in_sizes, int n_in,
                              void* d_out, int out_size)
{
    const float* x    = (const float*)d_in[0];
    const float* g_w  = (const float*)d_in[1];
    const float* g_b  = (const float*)d_in[2];
    const float* th_w = (const float*)d_in[3];
    const float* th_b = (const float*)d_in[4];
    const float* ph_w = (const float*)d_in[5];
    const float* ph_b = (const float*)d_in[6];
    const float* Ww   = (const float*)d_in[7];
    const float* Wb   = (const float*)d_in[8];
    float* out = (float*)d_out;

    const int SM1 = 52224;
    const int SM2 = 111104;
    const int SM3 = 73728;
    const int SM4 = 9216 + 128*72*2;                // 27648

    cudaFuncSetAttribute(k1_proj,  cudaFuncAttributeMaxDynamicSharedMemorySize, SM1);
    cudaFuncSetAttribute(k2_stats, cudaFuncAttributeMaxDynamicSharedMemorySize, SM2);
    cudaFuncSetAttribute(k3_attn,  cudaFuncAttributeMaxDynamicSharedMemorySize, SM3);
    cudaFuncSetAttribute(k4_out,   cudaFuncAttributeMaxDynamicSharedMemorySize, SM4);

    k1_proj <<<dim3(3, 256),    256, SM1>>>(x, g_w, g_b, th_w, th_b, ph_w, ph_b);
    k2_stats<<<dim3(32, 8),     256, SM2>>>();
    k3_attn <<<dim3(32, 8),     256, SM3>>>();
    k4_out  <<<dim3(2, 32, 8),  256, SM4>>>(x, Ww, Wb, out);
}

// round 14
// speedup vs baseline: 1.0313x; 1.0313x over previous
#include <cuda_runtime.h>
#include <cuda_fp16.h>
#include <cstdint>

// Problem constants
#define B_   8
#define C_   128
#define CI_  64
#define N_   4096
// P = 2^(s - SHIFT2), s = S*log2(e). SHIFT2=16: fp16 Inf only if S > 22.1 natural.
#define SHIFT2 16.0f
#define LOG2E  1.4426950408889634f

// ---------------- scratch (device globals; no allocations) ----------------
__device__ __half d_th  [B_*N_*CI_];   // theta*log2e [b][n][c]
__device__ __half d_phih[B_*N_*CI_];   // phi   [b][m][c]
__device__ __half d_g   [B_*CI_*N_];   // g     [b][c][m] (unscaled)
__device__ __half d_gih [B_*CI_*N_];   // g/Z   [b][c][m]
__device__ __half d_y   [B_*N_*CI_];   // y     [b][n][c]

// ---------------- helpers ----------------
// fp16 m16n8k16, fp32 accumulate
__device__ __forceinline__ void mmah(float* c, const unsigned* a, const unsigned* b) {
    asm volatile(
        "mma.sync.aligned.m16n8k16.row.col.f32.f16.f16.f32 "
        "{%0,%1,%2,%3},{%4,%5,%6,%7},{%8,%9},{%0,%1,%2,%3};\n"
        : "+f"(c[0]), "+f"(c[1]), "+f"(c[2]), "+f"(c[3])
        : "r"(a[0]), "r"(a[1]), "r"(a[2]), "r"(a[3]),
          "r"(b[0]), "r"(b[1]));
}

__device__ __forceinline__ void ldsm4(unsigned* r, unsigned addr) {
    asm volatile("ldmatrix.sync.aligned.m8n8.x4.shared.b16 {%0,%1,%2,%3}, [%4];"
        : "=r"(r[0]), "=r"(r[1]), "=r"(r[2]), "=r"(r[3]) : "r"(addr));
}

__device__ __forceinline__ void cpa16(void* dst_smem, const void* src) {
    unsigned d = (unsigned)__cvta_generic_to_shared(dst_smem);
    asm volatile("cp.async.cg.shared.global [%0], [%1], 16;" :: "r"(d), "l"(src));
}
#define CP_COMMIT()  asm volatile("cp.async.commit_group;")
#define CP_WAIT2()   asm volatile("cp.async.wait_group 2;")
#define CP_WAIT1()   asm volatile("cp.async.wait_group 1;")
#define CP_WAIT0()   asm volatile("cp.async.wait_group 0;")

__device__ __forceinline__ unsigned smem_u32(const void* p) {
    return (unsigned)__cvta_generic_to_shared(p);
}
// P pair = 2^(s - SHIFT2) through fp16 (identical path in k2 and k3)
__device__ __forceinline__ __half2 pexp2(float s0, float s1) {
    return h2exp2(__floats2half2_rn(s0 - SHIFT2, s1 - SHIFT2));
}

// =====================================================================
// K1: projections, fp16 m16n8k16. Staging map fixed vs R13: warp writes
// consecutive c (conflict-free STS), reads 16KB-strided float4 (L2-hit).
//   mtile 0: g -> d_g[c][m], 1: theta*log2e -> d_th[n][c], 2: phi -> d_phih[m][c]
// grid (3, 256), block 256. smem: As[64][136] + Bs[128][136] = 52224 B
// =====================================================================
__global__ void __launch_bounds__(256)
k1_proj(const float* __restrict__ x,
        const float* __restrict__ g_w,  const float* __restrict__ g_b,
        const float* __restrict__ th_w, const float* __restrict__ th_b,
        const float* __restrict__ ph_w, const float* __restrict__ ph_b)
{
    extern __shared__ char smc[];
    __half* As = reinterpret_cast<__half*>(smc);           // [64][136]
    __half* Bs = reinterpret_cast<__half*>(smc + 17408);   // [128][136]

    const int tid  = threadIdx.x;
    const int warp = tid >> 5, lane = tid & 31;
    const int g = lane >> 2, q = lane & 3;
    const int wr0 = (warp >> 2) * 32;   // m: 0 or 32
    const int wc0 = (warp & 3) * 32;    // n: 0,32,64,96

    const int mtile = blockIdx.x;
    const int ntot0 = blockIdx.y * 128;
    const int b  = ntot0 >> 12;
    const int n0 = ntot0 & (N_ - 1);

    const float* wsel = (mtile == 0) ? g_w : (mtile == 1 ? th_w : ph_w);
    const float* bsel = (mtile == 0) ? g_b : (mtile == 1 ? th_b : ph_b);
    const float wscale = (mtile == 1) ? LOG2E : 1.0f;

    // stage A: weights [64][128] fp32 -> fp16, scaled (coalesced, conflict-free)
    for (int i = tid; i < 64*32; i += 256) {
        int r = i >> 5, k4 = (i & 31) * 4;
        float4 v = *reinterpret_cast<const float4*>(wsel + r*128 + k4);
        __half2 h0 = __floats2half2_rn(v.x * wscale, v.y * wscale);
        __half2 h1 = __floats2half2_rn(v.z * wscale, v.w * wscale);
        *reinterpret_cast<__half2*>(As + r*136 + k4)     = h0;
        *reinterpret_cast<__half2*>(As + r*136 + k4 + 2) = h1;
    }
    // stage B: x^T tile -> Bs[n][c] fp16.
    // Warp holds consecutive c (32 lanes), fixed j4 -> STS to consecutive
    // half addresses (no bank conflicts). Reads are 16KB-strided float4
    // (32 sectors/instr) but x (16MB) is L2-resident across the 3 mtiles.
    for (int i = tid; i < 128*32; i += 256) {
        int c  = i & 127;
        int j4 = (i >> 7) * 4;
        float4 v = *reinterpret_cast<const float4*>(
            x + ((size_t)b*C_ + c) * N_ + n0 + j4);
        Bs[(j4    )*136 + c] = __float2half_rn(v.x);
        Bs[(j4 + 1)*136 + c] = __float2half_rn(v.y);
        Bs[(j4 + 2)*136 + c] = __float2half_rn(v.z);
        Bs[(j4 + 3)*136 + c] = __float2half_rn(v.w);
    }
    __syncthreads();

    // per-lane ldmatrix byte offsets (row stride = 272 B; 68 words -> lanes
    // land on banks 4 apart: conflict-free)
    const unsigned offA = smem_u32(As)
        + (unsigned)((wr0 + (lane & 15)) * 272 + (lane >> 4) * 16);
    const unsigned offB = smem_u32(Bs)
        + (unsigned)((wc0 + (lane & 7) + ((lane >> 4) << 3)) * 272
                     + ((lane >> 3) & 1) * 16);

    float acc[2][4][4];
    #pragma unroll
    for (int mi = 0; mi < 2; mi++)
        #pragma unroll
        for (int ni = 0; ni < 4; ni++)
            #pragma unroll
            for (int e = 0; e < 4; e++) acc[mi][ni][e] = 0.f;

    #pragma unroll
    for (int kj = 0; kj < 8; kj++) {
        unsigned a[2][4], bb[8];
        ldsm4(a[0], offA +        kj*32);
        ldsm4(a[1], offA + 4352 + kj*32);   // +16 rows (16*272)
        ldsm4(bb,     offB +        kj*32); // ni 0,1
        ldsm4(bb + 4, offB + 4352 + kj*32); // ni 2,3
        #pragma unroll
        for (int mi = 0; mi < 2; mi++)
            #pragma unroll
            for (int ni = 0; ni < 4; ni++)
                mmah(acc[mi][ni], a[mi], bb + ni*2);
    }

    #pragma unroll
    for (int mi = 0; mi < 2; mi++) {
        #pragma unroll
        for (int ni = 0; ni < 4; ni++) {
            #pragma unroll
            for (int e = 0; e < 4; e++) {
                int row = wr0 + mi*16 + g + ((e >> 1) * 8);   // out channel 0..63
                int col = wc0 + ni*8 + 2*q + (e & 1);         // spatial
                __half h = __float2half_rn(acc[mi][ni][e] + bsel[row]*wscale);
                int nglob = n0 + col;
                if (mtile == 0)
                    d_g[((size_t)b*CI_ + row) * N_ + nglob] = h;
                else if (mtile == 1)
                    d_th[((size_t)b*N_ + nglob) * CI_ + row] = h;
                else
                    d_phih[((size_t)b*N_ + nglob) * CI_ + row] = h;
            }
        }
    }
}

// =====================================================================
// K2: Z[m] = sum_n 2^(s[n,m]-SHIFT2); writes d_gih = g/Z ([c][m]).
// 128-query chunks (32 chunks), 4-deep theta ring, prefetch depth 2,
// ONE barrier per chunk. grid (32, 8), block 256. Unchanged from R12.
// =====================================================================
__global__ void __launch_bounds__(256, 2)
k2_stats()
{
    extern __shared__ char smc[];
    __half* phi_s = reinterpret_cast<__half*>(smc);            // [128][72]    18432 B
    __half* th_s  = reinterpret_cast<__half*>(smc + 18432);    // 4 x [128][72] 73728 B
    __half* g_s   = reinterpret_cast<__half*>(smc + 92160);    // [64][136]    17408 B
    float*  red   = reinterpret_cast<float*>(smc + 109568);    // 256 floats
    float*  cinv  = reinterpret_cast<float*>(smc + 110592);    // 128 floats

    const int tid  = threadIdx.x;
    const int warp = tid >> 5, lane = tid & 31;
    const int q = lane & 3;
    const int wr = warp >> 2;               // 0..1 (query half: rows wr*64..)
    const int wc = warp & 3;                // 0..3 (key cols)

    const int b  = blockIdx.y;
    const int m0 = blockIdx.x * 128;

    // stage phi key-tile [128 keys][64 c] + g tile [64 c][128 m] + th chunks 0,1
    const __half* phb = d_phih + ((size_t)b*N_ + m0) * CI_;
    for (int i = tid; i < 1024; i += 256) {
        int r = i >> 3, ch = (i & 7) * 8;
        cpa16(phi_s + r*72 + ch, phb + (size_t)r*CI_ + ch);
    }
    const __half* gsrc = d_g + (size_t)b*CI_*N_ + m0;
    for (int i = tid; i < 1024; i += 256) {
        int c = i >> 4, ch = (i & 15) * 8;
        cpa16(g_s + c*136 + ch, gsrc + (size_t)c*N_ + ch);
    }
    const __half* thb = d_th + (size_t)b*N_*CI_;
    for (int i = tid; i < 1024; i += 256) {
        int r = i >> 3, ch = (i & 7) * 8;
        cpa16(th_s + r*72 + ch, thb + (size_t)r*CI_ + ch);
    }
    CP_COMMIT();
    for (int i = tid; i < 1024; i += 256) {
        int r = i >> 3, ch = (i & 7) * 8;
        cpa16(th_s + 128*72 + r*72 + ch, thb + (size_t)(128 + r)*CI_ + ch);
    }
    CP_COMMIT();

    // per-lane ldmatrix byte offsets (row stride = 144 B)
    const unsigned offA = (unsigned)((wr*64 + (lane & 15)) * 144 + (lane >> 4) * 16);
    const unsigned offB = (unsigned)((wc*32 + (lane & 7) + (lane >> 4) * 8) * 144
                                     + ((lane >> 3) & 1) * 16);
    const unsigned phiB = smem_u32(phi_s) + offB;

    float zpart[8];
    #pragma unroll
    for (int i = 0; i < 8; i++) zpart[i] = 0.f;

    for (int ns = 0; ns < 32; ns++) {
        if (ns + 2 < 32) {
            __half* dst = th_s + ((ns + 2) & 3) * (128*72);
            const __half* src = thb + (size_t)(ns + 2)*128*CI_;
            for (int i = tid; i < 1024; i += 256) {
                int r = i >> 3, ch = (i & 7) * 8;
                cpa16(dst + r*72 + ch, src + (size_t)r*CI_ + ch);
            }
            CP_COMMIT();
            CP_WAIT2();
        } else if (ns + 1 < 32) {
            CP_WAIT1();
        } else {
            CP_WAIT0();
        }
        __syncthreads();   // single barrier per chunk (safe: 4-deep ring)
        const unsigned thA = smem_u32(th_s) + (unsigned)((ns & 3) * (128*72*2)) + offA;

        float acc[4][4][4];
        #pragma unroll
        for (int mi = 0; mi < 4; mi++)
            #pragma unroll
            for (int ni = 0; ni < 4; ni++)
                #pragma unroll
                for (int e = 0; e < 4; e++) acc[mi][ni][e] = 0.f;

        #pragma unroll
        for (int kj = 0; kj < 4; kj++) {
            unsigned bb[8];
            ldsm4(bb,     phiB + kj*32);          // ni 0,1
            ldsm4(bb + 4, phiB + 2304 + kj*32);   // ni 2,3
            #pragma unroll
            for (int mi = 0; mi < 4; mi++) {
                unsigned a[4];
                ldsm4(a, thA + mi*2304 + kj*32);  // 16 rows per mi (16*144=2304)
                #pragma unroll
                for (int ni = 0; ni < 4; ni++)
                    mmah(acc[mi][ni], a, bb + ni*2);
            }
        }

        // exp + Z partials
        #pragma unroll
        for (int ni = 0; ni < 4; ni++) {
            #pragma unroll
            for (int mi = 0; mi < 4; mi++) {
                float2 e0 = __half22float2(pexp2(acc[mi][ni][0], acc[mi][ni][1]));
                float2 e1 = __half22float2(pexp2(acc[mi][ni][2], acc[mi][ni][3]));
                zpart[ni*2    ] += e0.x + e1.x;
                zpart[ni*2 + 1] += e0.y + e1.y;
            }
        }
    }

    // reduce over g-lanes (xor 4, 8, 16)
    #pragma unroll
    for (int i = 0; i < 8; i++) {
        #pragma unroll
        for (int o = 4; o < 32; o <<= 1)
            zpart[i] += __shfl_xor_sync(0xffffffffu, zpart[i], o);
    }
    __syncthreads();
    if ((lane >> 2) == 0) {
        #pragma unroll
        for (int ni = 0; ni < 4; ni++)
            #pragma unroll
            for (int jj = 0; jj < 2; jj++)
                red[wr*128 + wc*32 + ni*8 + 2*q + jj] = zpart[ni*2 + jj];
    }
    __syncthreads();
    if (tid < 128) cinv[tid] = 1.0f / (red[tid] + red[128 + tid]);
    __syncthreads();

    // write g' = g * cinv to d_gih [c][m] (half2 along m, coalesced)
    for (int i = tid; i < 64*64; i += 256) {
        int c = i >> 6, mp = i & 63;
        __half2 gv = *reinterpret_cast<__half2*>(g_s + c*136 + 2*mp);
        float2 gf = __half22float2(gv);
        __half2 o = __floats2half2_rn(gf.x * cinv[2*mp], gf.y * cinv[2*mp + 1]);
        *reinterpret_cast<__half2*>(d_gih + ((size_t)b*CI_ + c) * N_ + m0 + 2*mp) = o;
    }
}

// =====================================================================
// K3: y = 2^(s-SHIFT2) @ g' (recompute). 4-deep ring, prefetch depth 2,
// ONE barrier per chunk. grid (32, 8), block 256. Unchanged from R12.
// =====================================================================
__global__ void __launch_bounds__(256, 2)
k3_attn()
{
    extern __shared__ char smc[];
    __half* phi_s = reinterpret_cast<__half*>(smc);            // 4 x [64][72]
    __half* gi_s  = reinterpret_cast<__half*>(smc + 36864);    // 4 x [64][72]

    const int tid  = threadIdx.x;
    const int warp = tid >> 5, lane = tid & 31;
    const int g = lane >> 2, q = lane & 3;
    const int rb = warp * 16;

    const int b  = blockIdx.y;
    const int n0 = blockIdx.x * 128;

    // hoist theta A-fragments (warp's 16 query rows, k=64 -> 4 chunks)
    unsigned a_th[4][4];
    {
        const __half* tb = d_th + ((size_t)b*N_ + n0 + rb) * CI_;
        #pragma unroll
        for (int kj = 0; kj < 4; kj++) {
            const __half* pc = tb + 16*kj + 2*q;
            a_th[kj][0] = *reinterpret_cast<const unsigned*>(pc + (size_t)g*CI_);
            a_th[kj][1] = *reinterpret_cast<const unsigned*>(pc + (size_t)(g+8)*CI_);
            a_th[kj][2] = *reinterpret_cast<const unsigned*>(pc + (size_t)g*CI_ + 8);
            a_th[kj][3] = *reinterpret_cast<const unsigned*>(pc + (size_t)(g+8)*CI_ + 8);
        }
    }

    // per-lane ldmatrix byte offset for B tiles (row stride 144 B)
    const unsigned offB = (unsigned)(((lane & 7) + (lane >> 4) * 8) * 144
                                     + ((lane >> 3) & 1) * 16);

    float yacc[8][4];
    #pragma unroll
    for (int ni = 0; ni < 8; ni++)
        #pragma unroll
        for (int e = 0; e < 4; e++) yacc[ni][e] = 0.f;

    const __half* phb = d_phih + (size_t)b*N_*CI_;
    const __half* gib = d_gih + (size_t)b*CI_*N_;

    // prologue: stage chunks 0 and 1 (separate commit groups)
    #pragma unroll
    for (int pc = 0; pc < 2; pc++) {
        __half* pd = phi_s + pc * (64*72);
        __half* gd = gi_s  + pc * (64*72);
        const int mm = pc * 64;
        for (int i = tid; i < 512; i += 256) {
            int r = i >> 3, ch = (i & 7) * 8;
            cpa16(pd + r*72 + ch, phb + (size_t)(mm + r)*CI_ + ch);
            cpa16(gd + r*72 + ch, gib + (size_t)r*N_ + mm + ch);
        }
        CP_COMMIT();
    }

    for (int ms = 0; ms < 64; ms++) {
        if (ms + 2 < 64) {
            const int m2 = (ms + 2) * 64;
            __half* pd = phi_s + ((ms + 2) & 3) * (64*72);
            __half* gd = gi_s  + ((ms + 2) & 3) * (64*72);
            for (int i = tid; i < 512; i += 256) {
                int r = i >> 3, ch = (i & 7) * 8;
                cpa16(pd + r*72 + ch, phb + (size_t)(m2 + r)*CI_ + ch);
                cpa16(gd + r*72 + ch, gib + (size_t)r*N_ + m2 + ch);
            }
            CP_COMMIT();
            CP_WAIT2();
        } else if (ms + 1 < 64) {
            CP_WAIT1();
        } else {
            CP_WAIT0();
        }
        __syncthreads();   // single barrier per chunk (safe: 4-deep ring)
        const unsigned pB = smem_u32(phi_s) + (unsigned)((ms & 3) * (64*72*2)) + offB;
        const unsigned gB = smem_u32(gi_s)  + (unsigned)((ms & 3) * (64*72*2)) + offB;

        // GEMM1: S tile 16x64 per warp
        float acc[8][4];
        #pragma unroll
        for (int ni = 0; ni < 8; ni++)
            #pragma unroll
            for (int e = 0; e < 4; e++) acc[ni][e] = 0.f;

        #pragma unroll
        for (int kj = 0; kj < 4; kj++) {
            unsigned bb[16];
            ldsm4(bb,      pB +        kj*32);   // ni 0,1
            ldsm4(bb + 4,  pB + 2304 + kj*32);   // ni 2,3
            ldsm4(bb + 8,  pB + 4608 + kj*32);   // ni 4,5
            ldsm4(bb + 12, pB + 6912 + kj*32);   // ni 6,7
            #pragma unroll
            for (int ni = 0; ni < 8; ni++)
                mmah(acc[ni], a_th[kj], bb + ni*2);
        }

        // P = 2^(S - SHIFT2) -> fp16 A-frags directly
        unsigned pA[8][2];
        #pragma unroll
        for (int ni = 0; ni < 8; ni++) {
            __half2 h0 = pexp2(acc[ni][0], acc[ni][1]);
            __half2 h1 = pexp2(acc[ni][2], acc[ni][3]);
            pA[ni][0] = *reinterpret_cast<unsigned*>(&h0);
            pA[ni][1] = *reinterpret_cast<unsigned*>(&h1);
        }

        // GEMM2: Y += P @ g'
        #pragma unroll
        for (int j = 0; j < 4; j++) {
            unsigned A[4] = { pA[2*j][0], pA[2*j][1], pA[2*j+1][0], pA[2*j+1][1] };
            unsigned bb[16];
            ldsm4(bb,      gB +        j*32);
            ldsm4(bb + 4,  gB + 2304 + j*32);
            ldsm4(bb + 8,  gB + 4608 + j*32);
            ldsm4(bb + 12, gB + 6912 + j*32);
            #pragma unroll
            for (int ni = 0; ni < 8; ni++)
                mmah(yacc[ni], A, bb + ni*2);
        }
    }

    // write Y (fp16, half2 pairs along c)
    #pragma unroll
    for (int ni = 0; ni < 8; ni++) {
        int row = n0 + rb + g;
        __half* base0 = d_y + ((size_t)b*N_ + row) * CI_ + ni*8 + 2*q;
        __half* base1 = d_y + ((size_t)b*N_ + row + 8) * CI_ + ni*8 + 2*q;
        *reinterpret_cast<__half2*>(base0) = __floats2half2_rn(yacc[ni][0], yacc[ni][1]);
        *reinterpret_cast<__half2*>(base1) = __floats2half2_rn(yacc[ni][2], yacc[ni][3]);
    }
}

// =====================================================================
// K4 (fp16 mma): out = W_w @ y^T + W_b + x. Unchanged.
// grid (2, 32, 8), block 256.
// =====================================================================
__global__ void __launch_bounds__(256, 3)
k4_out(const float* __restrict__ x,
       const float* __restrict__ Ww, const float* __restrict__ Wb,
       float* __restrict__ out)
{
    extern __shared__ char smc[];
    __half* Ws = reinterpret_cast<__half*>(smc);           // 64 x 72
    __half* Ys = reinterpret_cast<__half*>(smc + 9216);    // 128 x 72

    const int tid  = threadIdx.x;
    const int warp = tid >> 5, lane = tid & 31;
    const int g = lane >> 2, q = lane & 3;
    const int wr0 = (warp >> 2) * 32;
    const int wc0 = (warp & 3) * 32;

    const int co0 = blockIdx.x * 64;
    const int n0  = blockIdx.y * 128;
    const int b   = blockIdx.z;

    for (int i = tid; i < 1024; i += 256) {
        int r = i >> 3, ch = (i & 7) * 8;
        cpa16(Ys + r*72 + ch, d_y + ((size_t)b*N_ + n0 + r)*CI_ + ch);
    }
    CP_COMMIT();
    for (int i = tid; i < 64*16; i += 256) {
        int r = i >> 4, c4 = (i & 15) * 4;
        float4 v = *reinterpret_cast<const float4*>(Ww + (co0 + r)*CI_ + c4);
        __half2 h0 = __floats2half2_rn(v.x, v.y);
        __half2 h1 = __floats2half2_rn(v.z, v.w);
        *reinterpret_cast<__half2*>(Ws + r*72 + c4)     = h0;
        *reinterpret_cast<__half2*>(Ws + r*72 + c4 + 2) = h1;
    }
    CP_WAIT0();
    __syncthreads();

    float acc[2][4][4];
    #pragma unroll
    for (int mi = 0; mi < 2; mi++)
        #pragma unroll
        for (int ni = 0; ni < 4; ni++)
            #pragma unroll
            for (int e = 0; e < 4; e++) acc[mi][ni][e] = 0.f;

    #pragma unroll
    for (int kj = 0; kj < 4; kj++) {
        unsigned a[2][4], bb[4][2];
        #pragma unroll
        for (int mi = 0; mi < 2; mi++) {
            int r0 = wr0 + mi*16 + g;
            const __half* pr = Ws + 16*kj + 2*q;
            a[mi][0] = *reinterpret_cast<const unsigned*>(pr + (size_t)r0*72);
            a[mi][1] = *reinterpret_cast<const unsigned*>(pr + (size_t)(r0+8)*72);
            a[mi][2] = *reinterpret_cast<const unsigned*>(pr + (size_t)r0*72 + 8);
            a[mi][3] = *reinterpret_cast<const unsigned*>(pr + (size_t)(r0+8)*72 + 8);
        }
        #pragma unroll
        for (int ni = 0; ni < 4; ni++) {
            int col = wc0 + ni*8 + g;
            const __half* pc = Ys + (size_t)col*72 + 16*kj + 2*q;
            bb[ni][0] = *reinterpret_cast<const unsigned*>(pc);
            bb[ni][1] = *reinterpret_cast<const unsigned*>(pc + 8);
        }
        #pragma unroll
        for (int mi = 0; mi < 2; mi++)
            #pragma unroll
            for (int ni = 0; ni < 4; ni++)
                mmah(acc[mi][ni], a[mi], bb[ni]);
    }

    #pragma unroll
    for (int mi = 0; mi < 2; mi++) {
        #pragma unroll
        for (int ni = 0; ni < 4; ni++) {
            #pragma unroll
            for (int ep = 0; ep < 2; ep++) {
                int row = co0 + wr0 + mi*16 + g + ep*8;
                int col = n0 + wc0 + ni*8 + 2*q;
                size_t o = ((size_t)b*C_ + row) * N_ + col;
                float wb = Wb[row];
                float2 xv = *reinterpret_cast<const float2*>(x + o);
                float2 ov;
                ov.x = acc[mi][ni][ep*2    ] + wb + xv.x;
                ov.y = acc[mi][ni][ep*2 + 1] + wb + xv.y;
                *reinterpret_cast<float2*>(out + o) = ov;
            }
        }
    }
}

// =====================================================================
extern "C" void kernel_launch(void* const* d_in, const int* in_sizes, int n_in,
                              void* d_out, int out_size)
{
    const float* x    = (const float*)d_in[0];
    const float* g_w  = (const float*)d_in[1];
    const float* g_b  = (const float*)d_in[2];
    const float* th_w = (const float*)d_in[3];
    const float* th_b = (const float*)d_in[4];
    const float* ph_w = (const float*)d_in[5];
    const float* ph_b = (const float*)d_in[6];
    const float* Ww   = (const float*)d_in[7];
    const float* Wb   = (const float*)d_in[8];
    float* out = (float*)d_out;

    const int SM1 = 52224;
    const int SM2 = 111104;
    const int SM3 = 73728;
    const int SM4 = 9216 + 128*72*2;                // 27648

    cudaFuncSetAttribute(k1_proj,  cudaFuncAttributeMaxDynamicSharedMemorySize, SM1);
    cudaFuncSetAttribute(k2_stats, cudaFuncAttributeMaxDynamicSharedMemorySize, SM2);
    cudaFuncSetAttribute(k3_attn,  cudaFuncAttributeMaxDynamicSharedMemorySize, SM3);
    cudaFuncSetAttribute(k4_out,   cudaFuncAttributeMaxDynamicSharedMemorySize, SM4);

    k1_proj <<<dim3(3, 256),    256, SM1>>>(x, g_w, g_b, th_w, th_b, ph_w, ph_b);
    k2_stats<<<dim3(32, 8),     256, SM2>>>();
    k3_attn <<<dim3(32, 8),     256, SM3>>>();
    k4_out  <<<dim3(2, 32, 8),  256, SM4>>>(x, Ww, Wb, out);
}

// round 15
// speedup vs baseline: 1.1082x; 1.0746x over previous
#include <cuda_runtime.h>
#include <cuda_fp16.h>
#include <cstdint>

// Problem constants
#define B_   8
#define C_   128
#define CI_  64
#define N_   4096
// P = 2^(s - SHIFT2), s = S*log2(e). SHIFT2=16: fp16 Inf only if S > 22.1 natural.
#define SHIFT2 16.0f
#define LOG2E  1.4426950408889634f

// ---------------- scratch (device globals; no allocations) ----------------
__device__ __half d_th  [B_*N_*CI_];   // theta*log2e [b][n][c]
__device__ __half d_phih[B_*N_*CI_];   // phi   [b][m][c]
__device__ __half d_g   [B_*CI_*N_];   // g     [b][c][m] (unscaled)
__device__ __half d_gih [B_*CI_*N_];   // g/Z   [b][c][m]
__device__ __half d_y   [B_*N_*CI_];   // y     [b][n][c]

// ---------------- helpers ----------------
// fp16 m16n8k16, fp32 accumulate
__device__ __forceinline__ void mmah(float* c, const unsigned* a, const unsigned* b) {
    asm volatile(
        "mma.sync.aligned.m16n8k16.row.col.f32.f16.f16.f32 "
        "{%0,%1,%2,%3},{%4,%5,%6,%7},{%8,%9},{%0,%1,%2,%3};\n"
        : "+f"(c[0]), "+f"(c[1]), "+f"(c[2]), "+f"(c[3])
        : "r"(a[0]), "r"(a[1]), "r"(a[2]), "r"(a[3]),
          "r"(b[0]), "r"(b[1]));
}

__device__ __forceinline__ void ldsm4(unsigned* r, unsigned addr) {
    asm volatile("ldmatrix.sync.aligned.m8n8.x4.shared.b16 {%0,%1,%2,%3}, [%4];"
        : "=r"(r[0]), "=r"(r[1]), "=r"(r[2]), "=r"(r[3]) : "r"(addr));
}
// transposed variant: loads row-major [k][n] tiles as col-major B frags
__device__ __forceinline__ void ldsm4t(unsigned* r, unsigned addr) {
    asm volatile("ldmatrix.sync.aligned.m8n8.x4.trans.shared.b16 {%0,%1,%2,%3}, [%4];"
        : "=r"(r[0]), "=r"(r[1]), "=r"(r[2]), "=r"(r[3]) : "r"(addr));
}

__device__ __forceinline__ void cpa16(void* dst_smem, const void* src) {
    unsigned d = (unsigned)__cvta_generic_to_shared(dst_smem);
    asm volatile("cp.async.cg.shared.global [%0], [%1], 16;" :: "r"(d), "l"(src));
}
#define CP_COMMIT()  asm volatile("cp.async.commit_group;")
#define CP_WAIT2()   asm volatile("cp.async.wait_group 2;")
#define CP_WAIT1()   asm volatile("cp.async.wait_group 1;")
#define CP_WAIT0()   asm volatile("cp.async.wait_group 0;")

__device__ __forceinline__ unsigned smem_u32(const void* p) {
    return (unsigned)__cvta_generic_to_shared(p);
}
// P pair = 2^(s - SHIFT2) through fp16 (identical path in k2 and k3)
__device__ __forceinline__ __half2 pexp2(float s0, float s1) {
    return h2exp2(__floats2half2_rn(s0 - SHIFT2, s1 - SHIFT2));
}

// =====================================================================
// K1: projections, fp16 m16n8k16 with ldmatrix.trans for B.
// Staging is R12-style coalesced: Bs[c][n] row-major (float4 reads of x
// rows, consecutive-address STS). B-frags via ldmatrix.x4.trans.
//   mtile 0: g -> d_g[c][m], 1: theta*log2e -> d_th[n][c], 2: phi -> d_phih[m][c]
// grid (3, 256), block 256. smem: As[64][136] + Bs[128][136] = 52224 B
// =====================================================================
__global__ void __launch_bounds__(256)
k1_proj(const float* __restrict__ x,
        const float* __restrict__ g_w,  const float* __restrict__ g_b,
        const float* __restrict__ th_w, const float* __restrict__ th_b,
        const float* __restrict__ ph_w, const float* __restrict__ ph_b)
{
    extern __shared__ char smc[];
    __half* As = reinterpret_cast<__half*>(smc);           // [64 m][136] (k contiguous)
    __half* Bs = reinterpret_cast<__half*>(smc + 17408);   // [128 k][136] (n contiguous)

    const int tid  = threadIdx.x;
    const int warp = tid >> 5, lane = tid & 31;
    const int g = lane >> 2, q = lane & 3;
    const int wr0 = (warp >> 2) * 32;   // m: 0 or 32
    const int wc0 = (warp & 3) * 32;    // n: 0,32,64,96

    const int mtile = blockIdx.x;
    const int ntot0 = blockIdx.y * 128;
    const int b  = ntot0 >> 12;
    const int n0 = ntot0 & (N_ - 1);

    const float* wsel = (mtile == 0) ? g_w : (mtile == 1 ? th_w : ph_w);
    const float* bsel = (mtile == 0) ? g_b : (mtile == 1 ? th_b : ph_b);
    const float wscale = (mtile == 1) ? LOG2E : 1.0f;

    // stage A: weights [64][128] fp32 -> fp16, scaled (coalesced)
    for (int i = tid; i < 64*32; i += 256) {
        int r = i >> 5, k4 = (i & 31) * 4;
        float4 v = *reinterpret_cast<const float4*>(wsel + r*128 + k4);
        __half2 h0 = __floats2half2_rn(v.x * wscale, v.y * wscale);
        __half2 h1 = __floats2half2_rn(v.z * wscale, v.w * wscale);
        *reinterpret_cast<__half2*>(As + r*136 + k4)     = h0;
        *reinterpret_cast<__half2*>(As + r*136 + k4 + 2) = h1;
    }
    // stage B: x rows -> Bs[c][n] fp16 (coalesced float4 reads,
    // consecutive-address STS.64 -- conflict-free)
    for (int i = tid; i < 128*32; i += 256) {
        int c = i >> 5, j4 = (i & 31) * 4;
        float4 v = *reinterpret_cast<const float4*>(
            x + ((size_t)b*C_ + c) * N_ + n0 + j4);
        __half2 h0 = __floats2half2_rn(v.x, v.y);
        __half2 h1 = __floats2half2_rn(v.z, v.w);
        *reinterpret_cast<__half2*>(Bs + c*136 + j4)     = h0;
        *reinterpret_cast<__half2*>(Bs + c*136 + j4 + 2) = h1;
    }
    __syncthreads();

    // A frags: non-trans ldmatrix on [m][k] rows (row stride 272 B)
    const unsigned offA = smem_u32(As)
        + (unsigned)((wr0 + (lane & 15)) * 272 + (lane >> 4) * 16);
    // B frags: TRANS ldmatrix on [k][n] rows.
    // lanes 0-7: k0-7 @ n+0 | 8-15: k8-15 @ n+0 | 16-23: k0-7 @ n+8 | 24-31: k8-15 @ n+8
    const unsigned offBt = smem_u32(Bs)
        + (unsigned)(((lane & 7) + ((lane >> 3) & 1) * 8) * 272
                     + (lane >> 4) * 16 + wc0 * 2);

    float acc[2][4][4];
    #pragma unroll
    for (int mi = 0; mi < 2; mi++)
        #pragma unroll
        for (int ni = 0; ni < 4; ni++)
            #pragma unroll
            for (int e = 0; e < 4; e++) acc[mi][ni][e] = 0.f;

    #pragma unroll
    for (int kj = 0; kj < 8; kj++) {
        unsigned a[2][4], bb[8];
        ldsm4 (a[0], offA +        kj*32);
        ldsm4 (a[1], offA + 4352 + kj*32);   // +16 m rows (16*272)
        ldsm4t(bb,     offBt + kj*4352);      // ni 0,1 (n+0..15), k rows kj*16
        ldsm4t(bb + 4, offBt + kj*4352 + 32); // ni 2,3 (n+16..31)
        #pragma unroll
        for (int mi = 0; mi < 2; mi++)
            #pragma unroll
            for (int ni = 0; ni < 4; ni++)
                mmah(acc[mi][ni], a[mi], bb + ni*2);
    }

    #pragma unroll
    for (int mi = 0; mi < 2; mi++) {
        #pragma unroll
        for (int ni = 0; ni < 4; ni++) {
            #pragma unroll
            for (int e = 0; e < 4; e++) {
                int row = wr0 + mi*16 + g + ((e >> 1) * 8);   // out channel 0..63
                int col = wc0 + ni*8 + 2*q + (e & 1);         // spatial
                __half h = __float2half_rn(acc[mi][ni][e] + bsel[row]*wscale);
                int nglob = n0 + col;
                if (mtile == 0)
                    d_g[((size_t)b*CI_ + row) * N_ + nglob] = h;
                else if (mtile == 1)
                    d_th[((size_t)b*N_ + nglob) * CI_ + row] = h;
                else
                    d_phih[((size_t)b*N_ + nglob) * CI_ + row] = h;
            }
        }
    }
}

// =====================================================================
// K2: Z[m] = sum_n 2^(s[n,m]-SHIFT2); writes d_gih = g/Z ([c][m]).
// 128-query chunks (32 chunks), 4-deep theta ring, prefetch depth 2,
// ONE barrier per chunk. grid (32, 8), block 256. Unchanged from R12.
// =====================================================================
__global__ void __launch_bounds__(256, 2)
k2_stats()
{
    extern __shared__ char smc[];
    __half* phi_s = reinterpret_cast<__half*>(smc);            // [128][72]    18432 B
    __half* th_s  = reinterpret_cast<__half*>(smc + 18432);    // 4 x [128][72] 73728 B
    __half* g_s   = reinterpret_cast<__half*>(smc + 92160);    // [64][136]    17408 B
    float*  red   = reinterpret_cast<float*>(smc + 109568);    // 256 floats
    float*  cinv  = reinterpret_cast<float*>(smc + 110592);    // 128 floats

    const int tid  = threadIdx.x;
    const int warp = tid >> 5, lane = tid & 31;
    const int q = lane & 3;
    const int wr = warp >> 2;               // 0..1 (query half: rows wr*64..)
    const int wc = warp & 3;                // 0..3 (key cols)

    const int b  = blockIdx.y;
    const int m0 = blockIdx.x * 128;

    // stage phi key-tile [128 keys][64 c] + g tile [64 c][128 m] + th chunks 0,1
    const __half* phb = d_phih + ((size_t)b*N_ + m0) * CI_;
    for (int i = tid; i < 1024; i += 256) {
        int r = i >> 3, ch = (i & 7) * 8;
        cpa16(phi_s + r*72 + ch, phb + (size_t)r*CI_ + ch);
    }
    const __half* gsrc = d_g + (size_t)b*CI_*N_ + m0;
    for (int i = tid; i < 1024; i += 256) {
        int c = i >> 4, ch = (i & 15) * 8;
        cpa16(g_s + c*136 + ch, gsrc + (size_t)c*N_ + ch);
    }
    const __half* thb = d_th + (size_t)b*N_*CI_;
    for (int i = tid; i < 1024; i += 256) {
        int r = i >> 3, ch = (i & 7) * 8;
        cpa16(th_s + r*72 + ch, thb + (size_t)r*CI_ + ch);
    }
    CP_COMMIT();
    for (int i = tid; i < 1024; i += 256) {
        int r = i >> 3, ch = (i & 7) * 8;
        cpa16(th_s + 128*72 + r*72 + ch, thb + (size_t)(128 + r)*CI_ + ch);
    }
    CP_COMMIT();

    // per-lane ldmatrix byte offsets (row stride = 144 B)
    const unsigned offA = (unsigned)((wr*64 + (lane & 15)) * 144 + (lane >> 4) * 16);
    const unsigned offB = (unsigned)((wc*32 + (lane & 7) + (lane >> 4) * 8) * 144
                                     + ((lane >> 3) & 1) * 16);
    const unsigned phiB = smem_u32(phi_s) + offB;

    float zpart[8];
    #pragma unroll
    for (int i = 0; i < 8; i++) zpart[i] = 0.f;

    for (int ns = 0; ns < 32; ns++) {
        if (ns + 2 < 32) {
            __half* dst = th_s + ((ns + 2) & 3) * (128*72);
            const __half* src = thb + (size_t)(ns + 2)*128*CI_;
            for (int i = tid; i < 1024; i += 256) {
                int r = i >> 3, ch = (i & 7) * 8;
                cpa16(dst + r*72 + ch, src + (size_t)r*CI_ + ch);
            }
            CP_COMMIT();
            CP_WAIT2();
        } else if (ns + 1 < 32) {
            CP_WAIT1();
        } else {
            CP_WAIT0();
        }
        __syncthreads();   // single barrier per chunk (safe: 4-deep ring)
        const unsigned thA = smem_u32(th_s) + (unsigned)((ns & 3) * (128*72*2)) + offA;

        float acc[4][4][4];
        #pragma unroll
        for (int mi = 0; mi < 4; mi++)
            #pragma unroll
            for (int ni = 0; ni < 4; ni++)
                #pragma unroll
                for (int e = 0; e < 4; e++) acc[mi][ni][e] = 0.f;

        #pragma unroll
        for (int kj = 0; kj < 4; kj++) {
            unsigned bb[8];
            ldsm4(bb,     phiB + kj*32);          // ni 0,1
            ldsm4(bb + 4, phiB + 2304 + kj*32);   // ni 2,3
            #pragma unroll
            for (int mi = 0; mi < 4; mi++) {
                unsigned a[4];
                ldsm4(a, thA + mi*2304 + kj*32);  // 16 rows per mi (16*144=2304)
                #pragma unroll
                for (int ni = 0; ni < 4; ni++)
                    mmah(acc[mi][ni], a, bb + ni*2);
            }
        }

        // exp + Z partials
        #pragma unroll
        for (int ni = 0; ni < 4; ni++) {
            #pragma unroll
            for (int mi = 0; mi < 4; mi++) {
                float2 e0 = __half22float2(pexp2(acc[mi][ni][0], acc[mi][ni][1]));
                float2 e1 = __half22float2(pexp2(acc[mi][ni][2], acc[mi][ni][3]));
                zpart[ni*2    ] += e0.x + e1.x;
                zpart[ni*2 + 1] += e0.y + e1.y;
            }
        }
    }

    // reduce over g-lanes (xor 4, 8, 16)
    #pragma unroll
    for (int i = 0; i < 8; i++) {
        #pragma unroll
        for (int o = 4; o < 32; o <<= 1)
            zpart[i] += __shfl_xor_sync(0xffffffffu, zpart[i], o);
    }
    __syncthreads();
    if ((lane >> 2) == 0) {
        #pragma unroll
        for (int ni = 0; ni < 4; ni++)
            #pragma unroll
            for (int jj = 0; jj < 2; jj++)
                red[wr*128 + wc*32 + ni*8 + 2*q + jj] = zpart[ni*2 + jj];
    }
    __syncthreads();
    if (tid < 128) cinv[tid] = 1.0f / (red[tid] + red[128 + tid]);
    __syncthreads();

    // write g' = g * cinv to d_gih [c][m] (half2 along m, coalesced)
    for (int i = tid; i < 64*64; i += 256) {
        int c = i >> 6, mp = i & 63;
        __half2 gv = *reinterpret_cast<__half2*>(g_s + c*136 + 2*mp);
        float2 gf = __half22float2(gv);
        __half2 o = __floats2half2_rn(gf.x * cinv[2*mp], gf.y * cinv[2*mp + 1]);
        *reinterpret_cast<__half2*>(d_gih + ((size_t)b*CI_ + c) * N_ + m0 + 2*mp) = o;
    }
}

// =====================================================================
// K3: y = 2^(s-SHIFT2) @ g' (recompute). 4-deep ring, prefetch depth 2,
// ONE barrier per chunk. grid (32, 8), block 256. Unchanged from R12.
// =====================================================================
__global__ void __launch_bounds__(256, 2)
k3_attn()
{
    extern __shared__ char smc[];
    __half* phi_s = reinterpret_cast<__half*>(smc);            // 4 x [64][72]
    __half* gi_s  = reinterpret_cast<__half*>(smc + 36864);    // 4 x [64][72]

    const int tid  = threadIdx.x;
    const int warp = tid >> 5, lane = tid & 31;
    const int g = lane >> 2, q = lane & 3;
    const int rb = warp * 16;

    const int b  = blockIdx.y;
    const int n0 = blockIdx.x * 128;

    // hoist theta A-fragments (warp's 16 query rows, k=64 -> 4 chunks)
    unsigned a_th[4][4];
    {
        const __half* tb = d_th + ((size_t)b*N_ + n0 + rb) * CI_;
        #pragma unroll
        for (int kj = 0; kj < 4; kj++) {
            const __half* pc = tb + 16*kj + 2*q;
            a_th[kj][0] = *reinterpret_cast<const unsigned*>(pc + (size_t)g*CI_);
            a_th[kj][1] = *reinterpret_cast<const unsigned*>(pc + (size_t)(g+8)*CI_);
            a_th[kj][2] = *reinterpret_cast<const unsigned*>(pc + (size_t)g*CI_ + 8);
            a_th[kj][3] = *reinterpret_cast<const unsigned*>(pc + (size_t)(g+8)*CI_ + 8);
        }
    }

    // per-lane ldmatrix byte offset for B tiles (row stride 144 B)
    const unsigned offB = (unsigned)(((lane & 7) + (lane >> 4) * 8) * 144
                                     + ((lane >> 3) & 1) * 16);

    float yacc[8][4];
    #pragma unroll
    for (int ni = 0; ni < 8; ni++)
        #pragma unroll
        for (int e = 0; e < 4; e++) yacc[ni][e] = 0.f;

    const __half* phb = d_phih + (size_t)b*N_*CI_;
    const __half* gib = d_gih + (size_t)b*CI_*N_;

    // prologue: stage chunks 0 and 1 (separate commit groups)
    #pragma unroll
    for (int pc = 0; pc < 2; pc++) {
        __half* pd = phi_s + pc * (64*72);
        __half* gd = gi_s  + pc * (64*72);
        const int mm = pc * 64;
        for (int i = tid; i < 512; i += 256) {
            int r = i >> 3, ch = (i & 7) * 8;
            cpa16(pd + r*72 + ch, phb + (size_t)(mm + r)*CI_ + ch);
            cpa16(gd + r*72 + ch, gib + (size_t)r*N_ + mm + ch);
        }
        CP_COMMIT();
    }

    for (int ms = 0; ms < 64; ms++) {
        if (ms + 2 < 64) {
            const int m2 = (ms + 2) * 64;
            __half* pd = phi_s + ((ms + 2) & 3) * (64*72);
            __half* gd = gi_s  + ((ms + 2) & 3) * (64*72);
            for (int i = tid; i < 512; i += 256) {
                int r = i >> 3, ch = (i & 7) * 8;
                cpa16(pd + r*72 + ch, phb + (size_t)(m2 + r)*CI_ + ch);
                cpa16(gd + r*72 + ch, gib + (size_t)r*N_ + m2 + ch);
            }
            CP_COMMIT();
            CP_WAIT2();
        } else if (ms + 1 < 64) {
            CP_WAIT1();
        } else {
            CP_WAIT0();
        }
        __syncthreads();   // single barrier per chunk (safe: 4-deep ring)
        const unsigned pB = smem_u32(phi_s) + (unsigned)((ms & 3) * (64*72*2)) + offB;
        const unsigned gB = smem_u32(gi_s)  + (unsigned)((ms & 3) * (64*72*2)) + offB;

        // GEMM1: S tile 16x64 per warp
        float acc[8][4];
        #pragma unroll
        for (int ni = 0; ni < 8; ni++)
            #pragma unroll
            for (int e = 0; e < 4; e++) acc[ni][e] = 0.f;

        #pragma unroll
        for (int kj = 0; kj < 4; kj++) {
            unsigned bb[16];
            ldsm4(bb,      pB +        kj*32);   // ni 0,1
            ldsm4(bb + 4,  pB + 2304 + kj*32);   // ni 2,3
            ldsm4(bb + 8,  pB + 4608 + kj*32);   // ni 4,5
            ldsm4(bb + 12, pB + 6912 + kj*32);   // ni 6,7
            #pragma unroll
            for (int ni = 0; ni < 8; ni++)
                mmah(acc[ni], a_th[kj], bb + ni*2);
        }

        // P = 2^(S - SHIFT2) -> fp16 A-frags directly
        unsigned pA[8][2];
        #pragma unroll
        for (int ni = 0; ni < 8; ni++) {
            __half2 h0 = pexp2(acc[ni][0], acc[ni][1]);
            __half2 h1 = pexp2(acc[ni][2], acc[ni][3]);
            pA[ni][0] = *reinterpret_cast<unsigned*>(&h0);
            pA[ni][1] = *reinterpret_cast<unsigned*>(&h1);
        }

        // GEMM2: Y += P @ g'
        #pragma unroll
        for (int j = 0; j < 4; j++) {
            unsigned A[4] = { pA[2*j][0], pA[2*j][1], pA[2*j+1][0], pA[2*j+1][1] };
            unsigned bb[16];
            ldsm4(bb,      gB +        j*32);
            ldsm4(bb + 4,  gB + 2304 + j*32);
            ldsm4(bb + 8,  gB + 4608 + j*32);
            ldsm4(bb + 12, gB + 6912 + j*32);
            #pragma unroll
            for (int ni = 0; ni < 8; ni++)
                mmah(yacc[ni], A, bb + ni*2);
        }
    }

    // write Y (fp16, half2 pairs along c)
    #pragma unroll
    for (int ni = 0; ni < 8; ni++) {
        int row = n0 + rb + g;
        __half* base0 = d_y + ((size_t)b*N_ + row) * CI_ + ni*8 + 2*q;
        __half* base1 = d_y + ((size_t)b*N_ + row + 8) * CI_ + ni*8 + 2*q;
        *reinterpret_cast<__half2*>(base0) = __floats2half2_rn(yacc[ni][0], yacc[ni][1]);
        *reinterpret_cast<__half2*>(base1) = __floats2half2_rn(yacc[ni][2], yacc[ni][3]);
    }
}

// =====================================================================
// K4 (fp16 mma): out = W_w @ y^T + W_b + x. Unchanged.
// grid (2, 32, 8), block 256.
// =====================================================================
__global__ void __launch_bounds__(256, 3)
k4_out(const float* __restrict__ x,
       const float* __restrict__ Ww, const float* __restrict__ Wb,
       float* __restrict__ out)
{
    extern __shared__ char smc[];
    __half* Ws = reinterpret_cast<__half*>(smc);           // 64 x 72
    __half* Ys = reinterpret_cast<__half*>(smc + 9216);    // 128 x 72

    const int tid  = threadIdx.x;
    const int warp = tid >> 5, lane = tid & 31;
    const int g = lane >> 2, q = lane & 3;
    const int wr0 = (warp >> 2) * 32;
    const int wc0 = (warp & 3) * 32;

    const int co0 = blockIdx.x * 64;
    const int n0  = blockIdx.y * 128;
    const int b   = blockIdx.z;

    for (int i = tid; i < 1024; i += 256) {
        int r = i >> 3, ch = (i & 7) * 8;
        cpa16(Ys + r*72 + ch, d_y + ((size_t)b*N_ + n0 + r)*CI_ + ch);
    }
    CP_COMMIT();
    for (int i = tid; i < 64*16; i += 256) {
        int r = i >> 4, c4 = (i & 15) * 4;
        float4 v = *reinterpret_cast<const float4*>(Ww + (co0 + r)*CI_ + c4);
        __half2 h0 = __floats2half2_rn(v.x, v.y);
        __half2 h1 = __floats2half2_rn(v.z, v.w);
        *reinterpret_cast<__half2*>(Ws + r*72 + c4)     = h0;
        *reinterpret_cast<__half2*>(Ws + r*72 + c4 + 2) = h1;
    }
    CP_WAIT0();
    __syncthreads();

    float acc[2][4][4];
    #pragma unroll
    for (int mi = 0; mi < 2; mi++)
        #pragma unroll
        for (int ni = 0; ni < 4; ni++)
            #pragma unroll
            for (int e = 0; e < 4; e++) acc[mi][ni][e] = 0.f;

    #pragma unroll
    for (int kj = 0; kj < 4; kj++) {
        unsigned a[2][4], bb[4][2];
        #pragma unroll
        for (int mi = 0; mi < 2; mi++) {
            int r0 = wr0 + mi*16 + g;
            const __half* pr = Ws + 16*kj + 2*q;
            a[mi][0] = *reinterpret_cast<const unsigned*>(pr + (size_t)r0*72);
            a[mi][1] = *reinterpret_cast<const unsigned*>(pr + (size_t)(r0+8)*72);
            a[mi][2] = *reinterpret_cast<const unsigned*>(pr + (size_t)r0*72 + 8);
            a[mi][3] = *reinterpret_cast<const unsigned*>(pr + (size_t)(r0+8)*72 + 8);
        }
        #pragma unroll
        for (int ni = 0; ni < 4; ni++) {
            int col = wc0 + ni*8 + g;
            const __half* pc = Ys + (size_t)col*72 + 16*kj + 2*q;
            bb[ni][0] = *reinterpret_cast<const unsigned*>(pc);
            bb[ni][1] = *reinterpret_cast<const unsigned*>(pc + 8);
        }
        #pragma unroll
        for (int mi = 0; mi < 2; mi++)
            #pragma unroll
            for (int ni = 0; ni < 4; ni++)
                mmah(acc[mi][ni], a[mi], bb[ni]);
    }

    #pragma unroll
    for (int mi = 0; mi < 2; mi++) {
        #pragma unroll
        for (int ni = 0; ni < 4; ni++) {
            #pragma unroll
            for (int ep = 0; ep < 2; ep++) {
                int row = co0 + wr0 + mi*16 + g + ep*8;
                int col = n0 + wc0 + ni*8 + 2*q;
                size_t o = ((size_t)b*C_ + row) * N_ + col;
                float wb = Wb[row];
                float2 xv = *reinterpret_cast<const float2*>(x + o);
                float2 ov;
                ov.x = acc[mi][ni][ep*2    ] + wb + xv.x;
                ov.y = acc[mi][ni][ep*2 + 1] + wb + xv.y;
                *reinterpret_cast<float2*>(out + o) = ov;
            }
        }
    }
}

// =====================================================================
extern "C" void kernel_launch(void* const* d_in, const int* in_sizes, int n_in,
                              void* d_out, int out_size)
{
    const float* x    = (const float*)d_in[0];
    const float* g_w  = (const float*)d_in[1];
    const float* g_b  = (const float*)d_in[2];
    const float* th_w = (const float*)d_in[3];
    const float* th_b = (const float*)d_in[4];
    const float* ph_w = (const float*)d_in[5];
    const float* ph_b = (const float*)d_in[6];
    const float* Ww   = (const float*)d_in[7];
    const float* Wb   = (const float*)d_in[8];
    float* out = (float*)d_out;

    const int SM1 = 52224;
    const int SM2 = 111104;
    const int SM3 = 73728;
    const int SM4 = 9216 + 128*72*2;                // 27648

    cudaFuncSetAttribute(k1_proj,  cudaFuncAttributeMaxDynamicSharedMemorySize, SM1);
    cudaFuncSetAttribute(k2_stats, cudaFuncAttributeMaxDynamicSharedMemorySize, SM2);
    cudaFuncSetAttribute(k3_attn,  cudaFuncAttributeMaxDynamicSharedMemorySize, SM3);
    cudaFuncSetAttribute(k4_out,   cudaFuncAttributeMaxDynamicSharedMemorySize, SM4);

    k1_proj <<<dim3(3, 256),    256, SM1>>>(x, g_w, g_b, th_w, th_b, ph_w, ph_b);
    k2_stats<<<dim3(32, 8),     256, SM2>>>();
    k3_attn <<<dim3(32, 8),     256, SM3>>>();
    k4_out  <<<dim3(2, 32, 8),  256, SM4>>>(x, Ww, Wb, out);
}

// round 16
// speedup vs baseline: 1.1567x; 1.0438x over previous
#include <cuda_runtime.h>
#include <cuda_fp16.h>
#include <cstdint>

// Problem constants
#define B_   8
#define C_   128
#define CI_  64
#define N_   4096
// P = 2^(s - SHIFT2), s = S*log2(e). SHIFT2=16: fp16 Inf only if S > 22.1 natural.
#define SHIFT2 16.0f
#define LOG2E  1.4426950408889634f

// ---------------- scratch (device globals; no allocations) ----------------
__device__ __half d_th  [B_*N_*CI_];   // theta*log2e [b][n][c]
__device__ __half d_phih[B_*N_*CI_];   // phi   [b][m][c]
__device__ __half d_g   [B_*CI_*N_];   // g     [b][c][m] (unscaled)
__device__ __half d_gih [B_*CI_*N_];   // g/Z   [b][c][m]
__device__ __half d_y   [B_*N_*CI_];   // y     [b][n][c]

// ---------------- helpers ----------------
// fp16 m16n8k16, fp32 accumulate
__device__ __forceinline__ void mmah(float* c, const unsigned* a, const unsigned* b) {
    asm volatile(
        "mma.sync.aligned.m16n8k16.row.col.f32.f16.f16.f32 "
        "{%0,%1,%2,%3},{%4,%5,%6,%7},{%8,%9},{%0,%1,%2,%3};\n"
        : "+f"(c[0]), "+f"(c[1]), "+f"(c[2]), "+f"(c[3])
        : "r"(a[0]), "r"(a[1]), "r"(a[2]), "r"(a[3]),
          "r"(b[0]), "r"(b[1]));
}

__device__ __forceinline__ void ldsm4(unsigned* r, unsigned addr) {
    asm volatile("ldmatrix.sync.aligned.m8n8.x4.shared.b16 {%0,%1,%2,%3}, [%4];"
        : "=r"(r[0]), "=r"(r[1]), "=r"(r[2]), "=r"(r[3]) : "r"(addr));
}
// transposed variant: loads row-major [k][n] tiles as col-major B frags
__device__ __forceinline__ void ldsm4t(unsigned* r, unsigned addr) {
    asm volatile("ldmatrix.sync.aligned.m8n8.x4.trans.shared.b16 {%0,%1,%2,%3}, [%4];"
        : "=r"(r[0]), "=r"(r[1]), "=r"(r[2]), "=r"(r[3]) : "r"(addr));
}

__device__ __forceinline__ void cpa16(void* dst_smem, const void* src) {
    unsigned d = (unsigned)__cvta_generic_to_shared(dst_smem);
    asm volatile("cp.async.cg.shared.global [%0], [%1], 16;" :: "r"(d), "l"(src));
}
#define CP_COMMIT()  asm volatile("cp.async.commit_group;")
#define CP_WAIT2()   asm volatile("cp.async.wait_group 2;")
#define CP_WAIT1()   asm volatile("cp.async.wait_group 1;")
#define CP_WAIT0()   asm volatile("cp.async.wait_group 0;")

__device__ __forceinline__ unsigned smem_u32(const void* p) {
    return (unsigned)__cvta_generic_to_shared(p);
}
// P pair = 2^(s - SHIFT2) through fp16 (identical path in k2 and k3)
__device__ __forceinline__ __half2 pexp2(float s0, float s1) {
    return h2exp2(__floats2half2_rn(s0 - SHIFT2, s1 - SHIFT2));
}

// =====================================================================
// K1 (fused): all three projections in one block. x tile staged ONCE
// (was 3x in R15), all 192 weight rows resident. fp16 m16n8k16,
// ldmatrix.trans for B. grid (256) = one (b, n0) tile per block.
// smem: As[192][136] (52224 B) + Bs[128][136] (34816 B) = 87040 B, occ 2.
//   t=0: g -> d_g[c][m], t=1: theta*log2e -> d_th[n][c], t=2: phi -> d_phih[m][c]
// =====================================================================
__global__ void __launch_bounds__(256, 2)
k1_proj(const float* __restrict__ x,
        const float* __restrict__ g_w,  const float* __restrict__ g_b,
        const float* __restrict__ th_w, const float* __restrict__ th_b,
        const float* __restrict__ ph_w, const float* __restrict__ ph_b)
{
    extern __shared__ char smc[];
    __half* As = reinterpret_cast<__half*>(smc);           // [192 m][136] (k contiguous)
    __half* Bs = reinterpret_cast<__half*>(smc + 52224);   // [128 k][136] (n contiguous)

    const int tid  = threadIdx.x;
    const int warp = tid >> 5, lane = tid & 31;
    const int g = lane >> 2, q = lane & 3;
    const int wr0 = (warp >> 2) * 32;   // m within tensor: 0 or 32
    const int wc0 = (warp & 3) * 32;    // n: 0,32,64,96

    const int ntot0 = blockIdx.x * 128;
    const int b  = ntot0 >> 12;
    const int n0 = ntot0 & (N_ - 1);

    // stage all three weight tensors [64][128] each -> As rows [t*64 .. t*64+63]
    {
        const float* wsrc[3] = { g_w, th_w, ph_w };
        #pragma unroll
        for (int t = 0; t < 3; t++) {
            const float ws = (t == 1) ? LOG2E : 1.0f;
            for (int i = tid; i < 64*32; i += 256) {
                int r = i >> 5, k4 = (i & 31) * 4;
                float4 v = *reinterpret_cast<const float4*>(wsrc[t] + r*128 + k4);
                __half2 h0 = __floats2half2_rn(v.x * ws, v.y * ws);
                __half2 h1 = __floats2half2_rn(v.z * ws, v.w * ws);
                *reinterpret_cast<__half2*>(As + (t*64 + r)*136 + k4)     = h0;
                *reinterpret_cast<__half2*>(As + (t*64 + r)*136 + k4 + 2) = h1;
            }
        }
    }
    // stage B ONCE: x rows -> Bs[c][n] fp16 (coalesced float4 reads)
    for (int i = tid; i < 128*32; i += 256) {
        int c = i >> 5, j4 = (i & 31) * 4;
        float4 v = *reinterpret_cast<const float4*>(
            x + ((size_t)b*C_ + c) * N_ + n0 + j4);
        __half2 h0 = __floats2half2_rn(v.x, v.y);
        __half2 h1 = __floats2half2_rn(v.z, v.w);
        *reinterpret_cast<__half2*>(Bs + c*136 + j4)     = h0;
        *reinterpret_cast<__half2*>(Bs + c*136 + j4 + 2) = h1;
    }
    __syncthreads();

    // A frags: non-trans ldmatrix on [m][k] rows (row stride 272 B)
    const unsigned offA0 = smem_u32(As)
        + (unsigned)((wr0 + (lane & 15)) * 272 + (lane >> 4) * 16);
    // B frags: TRANS ldmatrix on [k][n] rows
    const unsigned offBt = smem_u32(Bs)
        + (unsigned)(((lane & 7) + ((lane >> 3) & 1) * 8) * 272
                     + (lane >> 4) * 16 + wc0 * 2);

    #pragma unroll
    for (int t = 0; t < 3; t++) {
        const float* bsel = (t == 0) ? g_b : (t == 1 ? th_b : ph_b);
        const float bscale = (t == 1) ? LOG2E : 1.0f;
        const unsigned offA = offA0 + (unsigned)(t * 64 * 272);

        float acc[2][4][4];
        #pragma unroll
        for (int mi = 0; mi < 2; mi++)
            #pragma unroll
            for (int ni = 0; ni < 4; ni++)
                #pragma unroll
                for (int e = 0; e < 4; e++) acc[mi][ni][e] = 0.f;

        #pragma unroll
        for (int kj = 0; kj < 8; kj++) {
            unsigned a[2][4], bb[8];
            ldsm4 (a[0], offA +        kj*32);
            ldsm4 (a[1], offA + 4352 + kj*32);    // +16 m rows (16*272)
            ldsm4t(bb,     offBt + kj*4352);       // ni 0,1 (n+0..15), k rows kj*16
            ldsm4t(bb + 4, offBt + kj*4352 + 32);  // ni 2,3 (n+16..31)
            #pragma unroll
            for (int mi = 0; mi < 2; mi++)
                #pragma unroll
                for (int ni = 0; ni < 4; ni++)
                    mmah(acc[mi][ni], a[mi], bb + ni*2);
        }

        #pragma unroll
        for (int mi = 0; mi < 2; mi++) {
            #pragma unroll
            for (int ni = 0; ni < 4; ni++) {
                #pragma unroll
                for (int e = 0; e < 4; e++) {
                    int row = wr0 + mi*16 + g + ((e >> 1) * 8);   // channel 0..63
                    int col = wc0 + ni*8 + 2*q + (e & 1);         // spatial
                    __half h = __float2half_rn(acc[mi][ni][e] + bsel[row]*bscale);
                    int nglob = n0 + col;
                    if (t == 0)
                        d_g[((size_t)b*CI_ + row) * N_ + nglob] = h;
                    else if (t == 1)
                        d_th[((size_t)b*N_ + nglob) * CI_ + row] = h;
                    else
                        d_phih[((size_t)b*N_ + nglob) * CI_ + row] = h;
                }
            }
        }
    }
}

// =====================================================================
// K2: Z[m] = sum_n 2^(s[n,m]-SHIFT2); writes d_gih = g/Z ([c][m]).
// 128-query chunks (32 chunks), 4-deep theta ring, prefetch depth 2,
// ONE barrier per chunk. grid (32, 8), block 256. Unchanged from R12.
// =====================================================================
__global__ void __launch_bounds__(256, 2)
k2_stats()
{
    extern __shared__ char smc[];
    __half* phi_s = reinterpret_cast<__half*>(smc);            // [128][72]    18432 B
    __half* th_s  = reinterpret_cast<__half*>(smc + 18432);    // 4 x [128][72] 73728 B
    __half* g_s   = reinterpret_cast<__half*>(smc + 92160);    // [64][136]    17408 B
    float*  red   = reinterpret_cast<float*>(smc + 109568);    // 256 floats
    float*  cinv  = reinterpret_cast<float*>(smc + 110592);    // 128 floats

    const int tid  = threadIdx.x;
    const int warp = tid >> 5, lane = tid & 31;
    const int q = lane & 3;
    const int wr = warp >> 2;               // 0..1 (query half: rows wr*64..)
    const int wc = warp & 3;                // 0..3 (key cols)

    const int b  = blockIdx.y;
    const int m0 = blockIdx.x * 128;

    // stage phi key-tile [128 keys][64 c] + g tile [64 c][128 m] + th chunks 0,1
    const __half* phb = d_phih + ((size_t)b*N_ + m0) * CI_;
    for (int i = tid; i < 1024; i += 256) {
        int r = i >> 3, ch = (i & 7) * 8;
        cpa16(phi_s + r*72 + ch, phb + (size_t)r*CI_ + ch);
    }
    const __half* gsrc = d_g + (size_t)b*CI_*N_ + m0;
    for (int i = tid; i < 1024; i += 256) {
        int c = i >> 4, ch = (i & 15) * 8;
        cpa16(g_s + c*136 + ch, gsrc + (size_t)c*N_ + ch);
    }
    const __half* thb = d_th + (size_t)b*N_*CI_;
    for (int i = tid; i < 1024; i += 256) {
        int r = i >> 3, ch = (i & 7) * 8;
        cpa16(th_s + r*72 + ch, thb + (size_t)r*CI_ + ch);
    }
    CP_COMMIT();
    for (int i = tid; i < 1024; i += 256) {
        int r = i >> 3, ch = (i & 7) * 8;
        cpa16(th_s + 128*72 + r*72 + ch, thb + (size_t)(128 + r)*CI_ + ch);
    }
    CP_COMMIT();

    // per-lane ldmatrix byte offsets (row stride = 144 B)
    const unsigned offA = (unsigned)((wr*64 + (lane & 15)) * 144 + (lane >> 4) * 16);
    const unsigned offB = (unsigned)((wc*32 + (lane & 7) + (lane >> 4) * 8) * 144
                                     + ((lane >> 3) & 1) * 16);
    const unsigned phiB = smem_u32(phi_s) + offB;

    float zpart[8];
    #pragma unroll
    for (int i = 0; i < 8; i++) zpart[i] = 0.f;

    for (int ns = 0; ns < 32; ns++) {
        if (ns + 2 < 32) {
            __half* dst = th_s + ((ns + 2) & 3) * (128*72);
            const __half* src = thb + (size_t)(ns + 2)*128*CI_;
            for (int i = tid; i < 1024; i += 256) {
                int r = i >> 3, ch = (i & 7) * 8;
                cpa16(dst + r*72 + ch, src + (size_t)r*CI_ + ch);
            }
            CP_COMMIT();
            CP_WAIT2();
        } else if (ns + 1 < 32) {
            CP_WAIT1();
        } else {
            CP_WAIT0();
        }
        __syncthreads();   // single barrier per chunk (safe: 4-deep ring)
        const unsigned thA = smem_u32(th_s) + (unsigned)((ns & 3) * (128*72*2)) + offA;

        float acc[4][4][4];
        #pragma unroll
        for (int mi = 0; mi < 4; mi++)
            #pragma unroll
            for (int ni = 0; ni < 4; ni++)
                #pragma unroll
                for (int e = 0; e < 4; e++) acc[mi][ni][e] = 0.f;

        #pragma unroll
        for (int kj = 0; kj < 4; kj++) {
            unsigned bb[8];
            ldsm4(bb,     phiB + kj*32);          // ni 0,1
            ldsm4(bb + 4, phiB + 2304 + kj*32);   // ni 2,3
            #pragma unroll
            for (int mi = 0; mi < 4; mi++) {
                unsigned a[4];
                ldsm4(a, thA + mi*2304 + kj*32);  // 16 rows per mi (16*144=2304)
                #pragma unroll
                for (int ni = 0; ni < 4; ni++)
                    mmah(acc[mi][ni], a, bb + ni*2);
            }
        }

        // exp + Z partials
        #pragma unroll
        for (int ni = 0; ni < 4; ni++) {
            #pragma unroll
            for (int mi = 0; mi < 4; mi++) {
                float2 e0 = __half22float2(pexp2(acc[mi][ni][0], acc[mi][ni][1]));
                float2 e1 = __half22float2(pexp2(acc[mi][ni][2], acc[mi][ni][3]));
                zpart[ni*2    ] += e0.x + e1.x;
                zpart[ni*2 + 1] += e0.y + e1.y;
            }
        }
    }

    // reduce over g-lanes (xor 4, 8, 16)
    #pragma unroll
    for (int i = 0; i < 8; i++) {
        #pragma unroll
        for (int o = 4; o < 32; o <<= 1)
            zpart[i] += __shfl_xor_sync(0xffffffffu, zpart[i], o);
    }
    __syncthreads();
    if ((lane >> 2) == 0) {
        #pragma unroll
        for (int ni = 0; ni < 4; ni++)
            #pragma unroll
            for (int jj = 0; jj < 2; jj++)
                red[wr*128 + wc*32 + ni*8 + 2*q + jj] = zpart[ni*2 + jj];
    }
    __syncthreads();
    if (tid < 128) cinv[tid] = 1.0f / (red[tid] + red[128 + tid]);
    __syncthreads();

    // write g' = g * cinv to d_gih [c][m] (half2 along m, coalesced)
    for (int i = tid; i < 64*64; i += 256) {
        int c = i >> 6, mp = i & 63;
        __half2 gv = *reinterpret_cast<__half2*>(g_s + c*136 + 2*mp);
        float2 gf = __half22float2(gv);
        __half2 o = __floats2half2_rn(gf.x * cinv[2*mp], gf.y * cinv[2*mp + 1]);
        *reinterpret_cast<__half2*>(d_gih + ((size_t)b*CI_ + c) * N_ + m0 + 2*mp) = o;
    }
}

// =====================================================================
// K3: y = 2^(s-SHIFT2) @ g' (recompute). 4-deep ring, prefetch depth 2,
// ONE barrier per chunk. grid (32, 8), block 256. Unchanged from R12.
// =====================================================================
__global__ void __launch_bounds__(256, 2)
k3_attn()
{
    extern __shared__ char smc[];
    __half* phi_s = reinterpret_cast<__half*>(smc);            // 4 x [64][72]
    __half* gi_s  = reinterpret_cast<__half*>(smc + 36864);    // 4 x [64][72]

    const int tid  = threadIdx.x;
    const int warp = tid >> 5, lane = tid & 31;
    const int g = lane >> 2, q = lane & 3;
    const int rb = warp * 16;

    const int b  = blockIdx.y;
    const int n0 = blockIdx.x * 128;

    // hoist theta A-fragments (warp's 16 query rows, k=64 -> 4 chunks)
    unsigned a_th[4][4];
    {
        const __half* tb = d_th + ((size_t)b*N_ + n0 + rb) * CI_;
        #pragma unroll
        for (int kj = 0; kj < 4; kj++) {
            const __half* pc = tb + 16*kj + 2*q;
            a_th[kj][0] = *reinterpret_cast<const unsigned*>(pc + (size_t)g*CI_);
            a_th[kj][1] = *reinterpret_cast<const unsigned*>(pc + (size_t)(g+8)*CI_);
            a_th[kj][2] = *reinterpret_cast<const unsigned*>(pc + (size_t)g*CI_ + 8);
            a_th[kj][3] = *reinterpret_cast<const unsigned*>(pc + (size_t)(g+8)*CI_ + 8);
        }
    }

    // per-lane ldmatrix byte offset for B tiles (row stride 144 B)
    const unsigned offB = (unsigned)(((lane & 7) + (lane >> 4) * 8) * 144
                                     + ((lane >> 3) & 1) * 16);

    float yacc[8][4];
    #pragma unroll
    for (int ni = 0; ni < 8; ni++)
        #pragma unroll
        for (int e = 0; e < 4; e++) yacc[ni][e] = 0.f;

    const __half* phb = d_phih + (size_t)b*N_*CI_;
    const __half* gib = d_gih + (size_t)b*CI_*N_;

    // prologue: stage chunks 0 and 1 (separate commit groups)
    #pragma unroll
    for (int pc = 0; pc < 2; pc++) {
        __half* pd = phi_s + pc * (64*72);
        __half* gd = gi_s  + pc * (64*72);
        const int mm = pc * 64;
        for (int i = tid; i < 512; i += 256) {
            int r = i >> 3, ch = (i & 7) * 8;
            cpa16(pd + r*72 + ch, phb + (size_t)(mm + r)*CI_ + ch);
            cpa16(gd + r*72 + ch, gib + (size_t)r*N_ + mm + ch);
        }
        CP_COMMIT();
    }

    for (int ms = 0; ms < 64; ms++) {
        if (ms + 2 < 64) {
            const int m2 = (ms + 2) * 64;
            __half* pd = phi_s + ((ms + 2) & 3) * (64*72);
            __half* gd = gi_s  + ((ms + 2) & 3) * (64*72);
            for (int i = tid; i < 512; i += 256) {
                int r = i >> 3, ch = (i & 7) * 8;
                cpa16(pd + r*72 + ch, phb + (size_t)(m2 + r)*CI_ + ch);
                cpa16(gd + r*72 + ch, gib + (size_t)r*N_ + m2 + ch);
            }
            CP_COMMIT();
            CP_WAIT2();
        } else if (ms + 1 < 64) {
            CP_WAIT1();
        } else {
            CP_WAIT0();
        }
        __syncthreads();   // single barrier per chunk (safe: 4-deep ring)
        const unsigned pB = smem_u32(phi_s) + (unsigned)((ms & 3) * (64*72*2)) + offB;
        const unsigned gB = smem_u32(gi_s)  + (unsigned)((ms & 3) * (64*72*2)) + offB;

        // GEMM1: S tile 16x64 per warp
        float acc[8][4];
        #pragma unroll
        for (int ni = 0; ni < 8; ni++)
            #pragma unroll
            for (int e = 0; e < 4; e++) acc[ni][e] = 0.f;

        #pragma unroll
        for (int kj = 0; kj < 4; kj++) {
            unsigned bb[16];
            ldsm4(bb,      pB +        kj*32);   // ni 0,1
            ldsm4(bb + 4,  pB + 2304 + kj*32);   // ni 2,3
            ldsm4(bb + 8,  pB + 4608 + kj*32);   // ni 4,5
            ldsm4(bb + 12, pB + 6912 + kj*32);   // ni 6,7
            #pragma unroll
            for (int ni = 0; ni < 8; ni++)
                mmah(acc[ni], a_th[kj], bb + ni*2);
        }

        // P = 2^(S - SHIFT2) -> fp16 A-frags directly
        unsigned pA[8][2];
        #pragma unroll
        for (int ni = 0; ni < 8; ni++) {
            __half2 h0 = pexp2(acc[ni][0], acc[ni][1]);
            __half2 h1 = pexp2(acc[ni][2], acc[ni][3]);
            pA[ni][0] = *reinterpret_cast<unsigned*>(&h0);
            pA[ni][1] = *reinterpret_cast<unsigned*>(&h1);
        }

        // GEMM2: Y += P @ g'
        #pragma unroll
        for (int j = 0; j < 4; j++) {
            unsigned A[4] = { pA[2*j][0], pA[2*j][1], pA[2*j+1][0], pA[2*j+1][1] };
            unsigned bb[16];
            ldsm4(bb,      gB +        j*32);
            ldsm4(bb + 4,  gB + 2304 + j*32);
            ldsm4(bb + 8,  gB + 4608 + j*32);
            ldsm4(bb + 12, gB + 6912 + j*32);
            #pragma unroll
            for (int ni = 0; ni < 8; ni++)
                mmah(yacc[ni], A, bb + ni*2);
        }
    }

    // write Y (fp16, half2 pairs along c)
    #pragma unroll
    for (int ni = 0; ni < 8; ni++) {
        int row = n0 + rb + g;
        __half* base0 = d_y + ((size_t)b*N_ + row) * CI_ + ni*8 + 2*q;
        __half* base1 = d_y + ((size_t)b*N_ + row + 8) * CI_ + ni*8 + 2*q;
        *reinterpret_cast<__half2*>(base0) = __floats2half2_rn(yacc[ni][0], yacc[ni][1]);
        *reinterpret_cast<__half2*>(base1) = __floats2half2_rn(yacc[ni][2], yacc[ni][3]);
    }
}

// =====================================================================
// K4 (fp16 mma): out = W_w @ y^T + W_b + x. Unchanged.
// grid (2, 32, 8), block 256.
// =====================================================================
__global__ void __launch_bounds__(256, 3)
k4_out(const float* __restrict__ x,
       const float* __restrict__ Ww, const float* __restrict__ Wb,
       float* __restrict__ out)
{
    extern __shared__ char smc[];
    __half* Ws = reinterpret_cast<__half*>(smc);           // 64 x 72
    __half* Ys = reinterpret_cast<__half*>(smc + 9216);    // 128 x 72

    const int tid  = threadIdx.x;
    const int warp = tid >> 5, lane = tid & 31;
    const int g = lane >> 2, q = lane & 3;
    const int wr0 = (warp >> 2) * 32;
    const int wc0 = (warp & 3) * 32;

    const int co0 = blockIdx.x * 64;
    const int n0  = blockIdx.y * 128;
    const int b   = blockIdx.z;

    for (int i = tid; i < 1024; i += 256) {
        int r = i >> 3, ch = (i & 7) * 8;
        cpa16(Ys + r*72 + ch, d_y + ((size_t)b*N_ + n0 + r)*CI_ + ch);
    }
    CP_COMMIT();
    for (int i = tid; i < 64*16; i += 256) {
        int r = i >> 4, c4 = (i & 15) * 4;
        float4 v = *reinterpret_cast<const float4*>(Ww + (co0 + r)*CI_ + c4);
        __half2 h0 = __floats2half2_rn(v.x, v.y);
        __half2 h1 = __floats2half2_rn(v.z, v.w);
        *reinterpret_cast<__half2*>(Ws + r*72 + c4)     = h0;
        *reinterpret_cast<__half2*>(Ws + r*72 + c4 + 2) = h1;
    }
    CP_WAIT0();
    __syncthreads();

    float acc[2][4][4];
    #pragma unroll
    for (int mi = 0; mi < 2; mi++)
        #pragma unroll
        for (int ni = 0; ni < 4; ni++)
            #pragma unroll
            for (int e = 0; e < 4; e++) acc[mi][ni][e] = 0.f;

    #pragma unroll
    for (int kj = 0; kj < 4; kj++) {
        unsigned a[2][4], bb[4][2];
        #pragma unroll
        for (int mi = 0; mi < 2; mi++) {
            int r0 = wr0 + mi*16 + g;
            const __half* pr = Ws + 16*kj + 2*q;
            a[mi][0] = *reinterpret_cast<const unsigned*>(pr + (size_t)r0*72);
            a[mi][1] = *reinterpret_cast<const unsigned*>(pr + (size_t)(r0+8)*72);
            a[mi][2] = *reinterpret_cast<const unsigned*>(pr + (size_t)r0*72 + 8);
            a[mi][3] = *reinterpret_cast<const unsigned*>(pr + (size_t)(r0+8)*72 + 8);
        }
        #pragma unroll
        for (int ni = 0; ni < 4; ni++) {
            int col = wc0 + ni*8 + g;
            const __half* pc = Ys + (size_t)col*72 + 16*kj + 2*q;
            bb[ni][0] = *reinterpret_cast<const unsigned*>(pc);
            bb[ni][1] = *reinterpret_cast<const unsigned*>(pc + 8);
        }
        #pragma unroll
        for (int mi = 0; mi < 2; mi++)
            #pragma unroll
            for (int ni = 0; ni < 4; ni++)
                mmah(acc[mi][ni], a[mi], bb[ni]);
    }

    #pragma unroll
    for (int mi = 0; mi < 2; mi++) {
        #pragma unroll
        for (int ni = 0; ni < 4; ni++) {
            #pragma unroll
            for (int ep = 0; ep < 2; ep++) {
                int row = co0 + wr0 + mi*16 + g + ep*8;
                int col = n0 + wc0 + ni*8 + 2*q;
                size_t o = ((size_t)b*C_ + row) * N_ + col;
                float wb = Wb[row];
                float2 xv = *reinterpret_cast<const float2*>(x + o);
                float2 ov;
                ov.x = acc[mi][ni][ep*2    ] + wb + xv.x;
                ov.y = acc[mi][ni][ep*2 + 1] + wb + xv.y;
                *reinterpret_cast<float2*>(out + o) = ov;
            }
        }
    }
}

// =====================================================================
extern "C" void kernel_launch(void* const* d_in, const int* in_sizes, int n_in,
                              void* d_out, int out_size)
{
    const float* x    = (const float*)d_in[0];
    const float* g_w  = (const float*)d_in[1];
    const float* g_b  = (const float*)d_in[2];
    const float* th_w = (const float*)d_in[3];
    const float* th_b = (const float*)d_in[4];
    const float* ph_w = (const float*)d_in[5];
    const float* ph_b = (const float*)d_in[6];
    const float* Ww   = (const float*)d_in[7];
    const float* Wb   = (const float*)d_in[8];
    float* out = (float*)d_out;

    const int SM1 = 87040;
    const int SM2 = 111104;
    const int SM3 = 73728;
    const int SM4 = 9216 + 128*72*2;                // 27648

    cudaFuncSetAttribute(k1_proj,  cudaFuncAttributeMaxDynamicSharedMemorySize, SM1);
    cudaFuncSetAttribute(k2_stats, cudaFuncAttributeMaxDynamicSharedMemorySize, SM2);
    cudaFuncSetAttribute(k3_attn,  cudaFuncAttributeMaxDynamicSharedMemorySize, SM3);
    cudaFuncSetAttribute(k4_out,   cudaFuncAttributeMaxDynamicSharedMemorySize, SM4);

    k1_proj <<<dim3(256),       256, SM1>>>(x, g_w, g_b, th_w, th_b, ph_w, ph_b);
    k2_stats<<<dim3(32, 8),     256, SM2>>>();
    k3_attn <<<dim3(32, 8),     256, SM3>>>();
    k4_out  <<<dim3(2, 32, 8),  256, SM4>>>(x, Ww, Wb, out);
}

// round 17
// speedup vs baseline: 1.1649x; 1.0071x over previous
#include <cuda_runtime.h>
#include <cuda_fp16.h>
#include <cstdint>

// Problem constants
#define B_   8
#define C_   128
#define CI_  64
#define N_   4096
// P = 2^(s - SHIFT2), s = S*log2(e). SHIFT2=16: fp16 Inf only if S > 22.1 natural.
#define SHIFT2 16.0f
#define LOG2E  1.4426950408889634f

// ---------------- scratch (device globals; no allocations) ----------------
__device__ __half d_th  [B_*N_*CI_];   // theta*log2e [b][n][c]
__device__ __half d_phih[B_*N_*CI_];   // phi   [b][m][c]
__device__ __half d_g   [B_*CI_*N_];   // g     [b][c][m] (unscaled)
__device__ __half d_gih [B_*CI_*N_];   // g/Z   [b][c][m]

// ---------------- helpers ----------------
// fp16 m16n8k16, fp32 accumulate
__device__ __forceinline__ void mmah(float* c, const unsigned* a, const unsigned* b) {
    asm volatile(
        "mma.sync.aligned.m16n8k16.row.col.f32.f16.f16.f32 "
        "{%0,%1,%2,%3},{%4,%5,%6,%7},{%8,%9},{%0,%1,%2,%3};\n"
        : "+f"(c[0]), "+f"(c[1]), "+f"(c[2]), "+f"(c[3])
        : "r"(a[0]), "r"(a[1]), "r"(a[2]), "r"(a[3]),
          "r"(b[0]), "r"(b[1]));
}

__device__ __forceinline__ void ldsm4(unsigned* r, unsigned addr) {
    asm volatile("ldmatrix.sync.aligned.m8n8.x4.shared.b16 {%0,%1,%2,%3}, [%4];"
        : "=r"(r[0]), "=r"(r[1]), "=r"(r[2]), "=r"(r[3]) : "r"(addr));
}
// transposed variant: loads row-major [k][n] tiles as col-major B frags
__device__ __forceinline__ void ldsm4t(unsigned* r, unsigned addr) {
    asm volatile("ldmatrix.sync.aligned.m8n8.x4.trans.shared.b16 {%0,%1,%2,%3}, [%4];"
        : "=r"(r[0]), "=r"(r[1]), "=r"(r[2]), "=r"(r[3]) : "r"(addr));
}

__device__ __forceinline__ void cpa16(void* dst_smem, const void* src) {
    unsigned d = (unsigned)__cvta_generic_to_shared(dst_smem);
    asm volatile("cp.async.cg.shared.global [%0], [%1], 16;" :: "r"(d), "l"(src));
}
#define CP_COMMIT()  asm volatile("cp.async.commit_group;")
#define CP_WAIT2()   asm volatile("cp.async.wait_group 2;")
#define CP_WAIT1()   asm volatile("cp.async.wait_group 1;")
#define CP_WAIT0()   asm volatile("cp.async.wait_group 0;")

__device__ __forceinline__ unsigned smem_u32(const void* p) {
    return (unsigned)__cvta_generic_to_shared(p);
}
// P pair = 2^(s - SHIFT2) through fp16 (identical path in k2 and k3)
__device__ __forceinline__ __half2 pexp2(float s0, float s1) {
    return h2exp2(__floats2half2_rn(s0 - SHIFT2, s1 - SHIFT2));
}

// =====================================================================
// K1 (fused): all three projections in one block. Unchanged from R16.
// grid (256), block 256. smem 87040 B, occ 2.
// =====================================================================
__global__ void __launch_bounds__(256, 2)
k1_proj(const float* __restrict__ x,
        const float* __restrict__ g_w,  const float* __restrict__ g_b,
        const float* __restrict__ th_w, const float* __restrict__ th_b,
        const float* __restrict__ ph_w, const float* __restrict__ ph_b)
{
    extern __shared__ char smc[];
    __half* As = reinterpret_cast<__half*>(smc);           // [192 m][136]
    __half* Bs = reinterpret_cast<__half*>(smc + 52224);   // [128 k][136]

    const int tid  = threadIdx.x;
    const int warp = tid >> 5, lane = tid & 31;
    const int g = lane >> 2, q = lane & 3;
    const int wr0 = (warp >> 2) * 32;
    const int wc0 = (warp & 3) * 32;

    const int ntot0 = blockIdx.x * 128;
    const int b  = ntot0 >> 12;
    const int n0 = ntot0 & (N_ - 1);

    {
        const float* wsrc[3] = { g_w, th_w, ph_w };
        #pragma unroll
        for (int t = 0; t < 3; t++) {
            const float ws = (t == 1) ? LOG2E : 1.0f;
            for (int i = tid; i < 64*32; i += 256) {
                int r = i >> 5, k4 = (i & 31) * 4;
                float4 v = *reinterpret_cast<const float4*>(wsrc[t] + r*128 + k4);
                __half2 h0 = __floats2half2_rn(v.x * ws, v.y * ws);
                __half2 h1 = __floats2half2_rn(v.z * ws, v.w * ws);
                *reinterpret_cast<__half2*>(As + (t*64 + r)*136 + k4)     = h0;
                *reinterpret_cast<__half2*>(As + (t*64 + r)*136 + k4 + 2) = h1;
            }
        }
    }
    for (int i = tid; i < 128*32; i += 256) {
        int c = i >> 5, j4 = (i & 31) * 4;
        float4 v = *reinterpret_cast<const float4*>(
            x + ((size_t)b*C_ + c) * N_ + n0 + j4);
        __half2 h0 = __floats2half2_rn(v.x, v.y);
        __half2 h1 = __floats2half2_rn(v.z, v.w);
        *reinterpret_cast<__half2*>(Bs + c*136 + j4)     = h0;
        *reinterpret_cast<__half2*>(Bs + c*136 + j4 + 2) = h1;
    }
    __syncthreads();

    const unsigned offA0 = smem_u32(As)
        + (unsigned)((wr0 + (lane & 15)) * 272 + (lane >> 4) * 16);
    const unsigned offBt = smem_u32(Bs)
        + (unsigned)(((lane & 7) + ((lane >> 3) & 1) * 8) * 272
                     + (lane >> 4) * 16 + wc0 * 2);

    #pragma unroll
    for (int t = 0; t < 3; t++) {
        const float* bsel = (t == 0) ? g_b : (t == 1 ? th_b : ph_b);
        const float bscale = (t == 1) ? LOG2E : 1.0f;
        const unsigned offA = offA0 + (unsigned)(t * 64 * 272);

        float acc[2][4][4];
        #pragma unroll
        for (int mi = 0; mi < 2; mi++)
            #pragma unroll
            for (int ni = 0; ni < 4; ni++)
                #pragma unroll
                for (int e = 0; e < 4; e++) acc[mi][ni][e] = 0.f;

        #pragma unroll
        for (int kj = 0; kj < 8; kj++) {
            unsigned a[2][4], bb[8];
            ldsm4 (a[0], offA +        kj*32);
            ldsm4 (a[1], offA + 4352 + kj*32);
            ldsm4t(bb,     offBt + kj*4352);
            ldsm4t(bb + 4, offBt + kj*4352 + 32);
            #pragma unroll
            for (int mi = 0; mi < 2; mi++)
                #pragma unroll
                for (int ni = 0; ni < 4; ni++)
                    mmah(acc[mi][ni], a[mi], bb + ni*2);
        }

        #pragma unroll
        for (int mi = 0; mi < 2; mi++) {
            #pragma unroll
            for (int ni = 0; ni < 4; ni++) {
                #pragma unroll
                for (int e = 0; e < 4; e++) {
                    int row = wr0 + mi*16 + g + ((e >> 1) * 8);
                    int col = wc0 + ni*8 + 2*q + (e & 1);
                    __half h = __float2half_rn(acc[mi][ni][e] + bsel[row]*bscale);
                    int nglob = n0 + col;
                    if (t == 0)
                        d_g[((size_t)b*CI_ + row) * N_ + nglob] = h;
                    else if (t == 1)
                        d_th[((size_t)b*N_ + nglob) * CI_ + row] = h;
                    else
                        d_phih[((size_t)b*N_ + nglob) * CI_ + row] = h;
                }
            }
        }
    }
}

// =====================================================================
// K2: Z[m] = sum_n 2^(s[n,m]-SHIFT2); writes d_gih = g/Z ([c][m]).
// Unchanged from R12/R16. grid (32, 8), block 256.
// =====================================================================
__global__ void __launch_bounds__(256, 2)
k2_stats()
{
    extern __shared__ char smc[];
    __half* phi_s = reinterpret_cast<__half*>(smc);            // [128][72]
    __half* th_s  = reinterpret_cast<__half*>(smc + 18432);    // 4 x [128][72]
    __half* g_s   = reinterpret_cast<__half*>(smc + 92160);    // [64][136]
    float*  red   = reinterpret_cast<float*>(smc + 109568);    // 256
    float*  cinv  = reinterpret_cast<float*>(smc + 110592);    // 128

    const int tid  = threadIdx.x;
    const int warp = tid >> 5, lane = tid & 31;
    const int q = lane & 3;
    const int wr = warp >> 2;
    const int wc = warp & 3;

    const int b  = blockIdx.y;
    const int m0 = blockIdx.x * 128;

    const __half* phb = d_phih + ((size_t)b*N_ + m0) * CI_;
    for (int i = tid; i < 1024; i += 256) {
        int r = i >> 3, ch = (i & 7) * 8;
        cpa16(phi_s + r*72 + ch, phb + (size_t)r*CI_ + ch);
    }
    const __half* gsrc = d_g + (size_t)b*CI_*N_ + m0;
    for (int i = tid; i < 1024; i += 256) {
        int c = i >> 4, ch = (i & 15) * 8;
        cpa16(g_s + c*136 + ch, gsrc + (size_t)c*N_ + ch);
    }
    const __half* thb = d_th + (size_t)b*N_*CI_;
    for (int i = tid; i < 1024; i += 256) {
        int r = i >> 3, ch = (i & 7) * 8;
        cpa16(th_s + r*72 + ch, thb + (size_t)r*CI_ + ch);
    }
    CP_COMMIT();
    for (int i = tid; i < 1024; i += 256) {
        int r = i >> 3, ch = (i & 7) * 8;
        cpa16(th_s + 128*72 + r*72 + ch, thb + (size_t)(128 + r)*CI_ + ch);
    }
    CP_COMMIT();

    const unsigned offA = (unsigned)((wr*64 + (lane & 15)) * 144 + (lane >> 4) * 16);
    const unsigned offB = (unsigned)((wc*32 + (lane & 7) + (lane >> 4) * 8) * 144
                                     + ((lane >> 3) & 1) * 16);
    const unsigned phiB = smem_u32(phi_s) + offB;

    float zpart[8];
    #pragma unroll
    for (int i = 0; i < 8; i++) zpart[i] = 0.f;

    for (int ns = 0; ns < 32; ns++) {
        if (ns + 2 < 32) {
            __half* dst = th_s + ((ns + 2) & 3) * (128*72);
            const __half* src = thb + (size_t)(ns + 2)*128*CI_;
            for (int i = tid; i < 1024; i += 256) {
                int r = i >> 3, ch = (i & 7) * 8;
                cpa16(dst + r*72 + ch, src + (size_t)r*CI_ + ch);
            }
            CP_COMMIT();
            CP_WAIT2();
        } else if (ns + 1 < 32) {
            CP_WAIT1();
        } else {
            CP_WAIT0();
        }
        __syncthreads();
        const unsigned thA = smem_u32(th_s) + (unsigned)((ns & 3) * (128*72*2)) + offA;

        float acc[4][4][4];
        #pragma unroll
        for (int mi = 0; mi < 4; mi++)
            #pragma unroll
            for (int ni = 0; ni < 4; ni++)
                #pragma unroll
                for (int e = 0; e < 4; e++) acc[mi][ni][e] = 0.f;

        #pragma unroll
        for (int kj = 0; kj < 4; kj++) {
            unsigned bb[8];
            ldsm4(bb,     phiB + kj*32);
            ldsm4(bb + 4, phiB + 2304 + kj*32);
            #pragma unroll
            for (int mi = 0; mi < 4; mi++) {
                unsigned a[4];
                ldsm4(a, thA + mi*2304 + kj*32);
                #pragma unroll
                for (int ni = 0; ni < 4; ni++)
                    mmah(acc[mi][ni], a, bb + ni*2);
            }
        }

        #pragma unroll
        for (int ni = 0; ni < 4; ni++) {
            #pragma unroll
            for (int mi = 0; mi < 4; mi++) {
                float2 e0 = __half22float2(pexp2(acc[mi][ni][0], acc[mi][ni][1]));
                float2 e1 = __half22float2(pexp2(acc[mi][ni][2], acc[mi][ni][3]));
                zpart[ni*2    ] += e0.x + e1.x;
                zpart[ni*2 + 1] += e0.y + e1.y;
            }
        }
    }

    #pragma unroll
    for (int i = 0; i < 8; i++) {
        #pragma unroll
        for (int o = 4; o < 32; o <<= 1)
            zpart[i] += __shfl_xor_sync(0xffffffffu, zpart[i], o);
    }
    __syncthreads();
    if ((lane >> 2) == 0) {
        #pragma unroll
        for (int ni = 0; ni < 4; ni++)
            #pragma unroll
            for (int jj = 0; jj < 2; jj++)
                red[wr*128 + wc*32 + ni*8 + 2*q + jj] = zpart[ni*2 + jj];
    }
    __syncthreads();
    if (tid < 128) cinv[tid] = 1.0f / (red[tid] + red[128 + tid]);
    __syncthreads();

    for (int i = tid; i < 64*64; i += 256) {
        int c = i >> 6, mp = i & 63;
        __half2 gv = *reinterpret_cast<__half2*>(g_s + c*136 + 2*mp);
        float2 gf = __half22float2(gv);
        __half2 o = __floats2half2_rn(gf.x * cinv[2*mp], gf.y * cinv[2*mp + 1]);
        *reinterpret_cast<__half2*>(d_gih + ((size_t)b*CI_ + c) * N_ + m0 + 2*mp) = o;
    }
}

// =====================================================================
// K3 (fused with k4): y = 2^(s-SHIFT2) @ g', then out = Ww @ y^T + Wb + x
// in the same block. Mainloop unchanged from R12. Epilogue: y frags ->
// smem Ys[128][72], barrier, k4-style GEMM vs block-resident Ws[128][72]
// (staged once at start), direct out writes with x residual.
// grid (32, 8), block 256.
// smem: ring 73728 + Ws 18432 + Ys 18432 = 110592 B, occ 2.
// =====================================================================
__global__ void __launch_bounds__(256, 2)
k3_attn(const float* __restrict__ x,
        const float* __restrict__ Ww, const float* __restrict__ Wb,
        float* __restrict__ out)
{
    extern __shared__ char smc[];
    __half* phi_s = reinterpret_cast<__half*>(smc);            // 4 x [64][72]
    __half* gi_s  = reinterpret_cast<__half*>(smc + 36864);    // 4 x [64][72]
    __half* Ws    = reinterpret_cast<__half*>(smc + 73728);    // [128][72]
    __half* Ys    = reinterpret_cast<__half*>(smc + 92160);    // [128][72]

    const int tid  = threadIdx.x;
    const int warp = tid >> 5, lane = tid & 31;
    const int g = lane >> 2, q = lane & 3;
    const int rb = warp * 16;

    const int b  = blockIdx.y;
    const int n0 = blockIdx.x * 128;

    // stage Ws once: Ww [128][64] fp32 -> fp16 (read after mainloop;
    // ordering guaranteed by the mainloop barriers)
    for (int i = tid; i < 128*16; i += 256) {
        int r = i >> 4, c4 = (i & 15) * 4;
        float4 v = *reinterpret_cast<const float4*>(Ww + r*CI_ + c4);
        __half2 h0 = __floats2half2_rn(v.x, v.y);
        __half2 h1 = __floats2half2_rn(v.z, v.w);
        *reinterpret_cast<__half2*>(Ws + r*72 + c4)     = h0;
        *reinterpret_cast<__half2*>(Ws + r*72 + c4 + 2) = h1;
    }

    // hoist theta A-fragments (warp's 16 query rows, k=64 -> 4 chunks)
    unsigned a_th[4][4];
    {
        const __half* tb = d_th + ((size_t)b*N_ + n0 + rb) * CI_;
        #pragma unroll
        for (int kj = 0; kj < 4; kj++) {
            const __half* pc = tb + 16*kj + 2*q;
            a_th[kj][0] = *reinterpret_cast<const unsigned*>(pc + (size_t)g*CI_);
            a_th[kj][1] = *reinterpret_cast<const unsigned*>(pc + (size_t)(g+8)*CI_);
            a_th[kj][2] = *reinterpret_cast<const unsigned*>(pc + (size_t)g*CI_ + 8);
            a_th[kj][3] = *reinterpret_cast<const unsigned*>(pc + (size_t)(g+8)*CI_ + 8);
        }
    }

    // per-lane ldmatrix byte offset for B tiles (row stride 144 B)
    const unsigned offB = (unsigned)(((lane & 7) + (lane >> 4) * 8) * 144
                                     + ((lane >> 3) & 1) * 16);

    float yacc[8][4];
    #pragma unroll
    for (int ni = 0; ni < 8; ni++)
        #pragma unroll
        for (int e = 0; e < 4; e++) yacc[ni][e] = 0.f;

    const __half* phb = d_phih + (size_t)b*N_*CI_;
    const __half* gib = d_gih + (size_t)b*CI_*N_;

    // prologue: stage chunks 0 and 1 (separate commit groups)
    #pragma unroll
    for (int pc = 0; pc < 2; pc++) {
        __half* pd = phi_s + pc * (64*72);
        __half* gd = gi_s  + pc * (64*72);
        const int mm = pc * 64;
        for (int i = tid; i < 512; i += 256) {
            int r = i >> 3, ch = (i & 7) * 8;
            cpa16(pd + r*72 + ch, phb + (size_t)(mm + r)*CI_ + ch);
            cpa16(gd + r*72 + ch, gib + (size_t)r*N_ + mm + ch);
        }
        CP_COMMIT();
    }

    for (int ms = 0; ms < 64; ms++) {
        if (ms + 2 < 64) {
            const int m2 = (ms + 2) * 64;
            __half* pd = phi_s + ((ms + 2) & 3) * (64*72);
            __half* gd = gi_s  + ((ms + 2) & 3) * (64*72);
            for (int i = tid; i < 512; i += 256) {
                int r = i >> 3, ch = (i & 7) * 8;
                cpa16(pd + r*72 + ch, phb + (size_t)(m2 + r)*CI_ + ch);
                cpa16(gd + r*72 + ch, gib + (size_t)r*N_ + m2 + ch);
            }
            CP_COMMIT();
            CP_WAIT2();
        } else if (ms + 1 < 64) {
            CP_WAIT1();
        } else {
            CP_WAIT0();
        }
        __syncthreads();   // single barrier per chunk (safe: 4-deep ring)
        const unsigned pB = smem_u32(phi_s) + (unsigned)((ms & 3) * (64*72*2)) + offB;
        const unsigned gB = smem_u32(gi_s)  + (unsigned)((ms & 3) * (64*72*2)) + offB;

        // GEMM1: S tile 16x64 per warp
        float acc[8][4];
        #pragma unroll
        for (int ni = 0; ni < 8; ni++)
            #pragma unroll
            for (int e = 0; e < 4; e++) acc[ni][e] = 0.f;

        #pragma unroll
        for (int kj = 0; kj < 4; kj++) {
            unsigned bb[16];
            ldsm4(bb,      pB +        kj*32);
            ldsm4(bb + 4,  pB + 2304 + kj*32);
            ldsm4(bb + 8,  pB + 4608 + kj*32);
            ldsm4(bb + 12, pB + 6912 + kj*32);
            #pragma unroll
            for (int ni = 0; ni < 8; ni++)
                mmah(acc[ni], a_th[kj], bb + ni*2);
        }

        // P = 2^(S - SHIFT2) -> fp16 A-frags directly
        unsigned pA[8][2];
        #pragma unroll
        for (int ni = 0; ni < 8; ni++) {
            __half2 h0 = pexp2(acc[ni][0], acc[ni][1]);
            __half2 h1 = pexp2(acc[ni][2], acc[ni][3]);
            pA[ni][0] = *reinterpret_cast<unsigned*>(&h0);
            pA[ni][1] = *reinterpret_cast<unsigned*>(&h1);
        }

        // GEMM2: Y += P @ g'
        #pragma unroll
        for (int j = 0; j < 4; j++) {
            unsigned A[4] = { pA[2*j][0], pA[2*j][1], pA[2*j+1][0], pA[2*j+1][1] };
            unsigned bb[16];
            ldsm4(bb,      gB +        j*32);
            ldsm4(bb + 4,  gB + 2304 + j*32);
            ldsm4(bb + 8,  gB + 4608 + j*32);
            ldsm4(bb + 12, gB + 6912 + j*32);
            #pragma unroll
            for (int ni = 0; ni < 8; ni++)
                mmah(yacc[ni], A, bb + ni*2);
        }
    }

    // ---- fused k4 epilogue ----
    // write Y frags to smem Ys[n][c] (same fp16 values as the old d_y)
    #pragma unroll
    for (int ni = 0; ni < 8; ni++) {
        int row = rb + g;
        *reinterpret_cast<__half2*>(Ys + row*72 + ni*8 + 2*q) =
            __floats2half2_rn(yacc[ni][0], yacc[ni][1]);
        *reinterpret_cast<__half2*>(Ys + (row + 8)*72 + ni*8 + 2*q) =
            __floats2half2_rn(yacc[ni][2], yacc[ni][3]);
    }
    __syncthreads();

    // out[cout][n0..n0+127] = Ws @ Ys^T + Wb + x  (k4's proven warp layout,
    // run twice for cout halves 0 and 64)
    const int wr0 = (warp >> 2) * 32;
    const int wc0 = (warp & 3) * 32;

    #pragma unroll
    for (int mo = 0; mo < 2; mo++) {
        const int cb = mo * 64;

        float acc[2][4][4];
        #pragma unroll
        for (int mi = 0; mi < 2; mi++)
            #pragma unroll
            for (int ni = 0; ni < 4; ni++)
                #pragma unroll
                for (int e = 0; e < 4; e++) acc[mi][ni][e] = 0.f;

        #pragma unroll
        for (int kj = 0; kj < 4; kj++) {
            unsigned a[2][4], bb[4][2];
            #pragma unroll
            for (int mi = 0; mi < 2; mi++) {
                int r0 = cb + wr0 + mi*16 + g;
                const __half* pr = Ws + 16*kj + 2*q;
                a[mi][0] = *reinterpret_cast<const unsigned*>(pr + (size_t)r0*72);
                a[mi][1] = *reinterpret_cast<const unsigned*>(pr + (size_t)(r0+8)*72);
                a[mi][2] = *reinterpret_cast<const unsigned*>(pr + (size_t)r0*72 + 8);
                a[mi][3] = *reinterpret_cast<const unsigned*>(pr + (size_t)(r0+8)*72 + 8);
            }
            #pragma unroll
            for (int ni = 0; ni < 4; ni++) {
                int col = wc0 + ni*8 + g;
                const __half* pc = Ys + (size_t)col*72 + 16*kj + 2*q;
                bb[ni][0] = *reinterpret_cast<const unsigned*>(pc);
                bb[ni][1] = *reinterpret_cast<const unsigned*>(pc + 8);
            }
            #pragma unroll
            for (int mi = 0; mi < 2; mi++)
                #pragma unroll
                for (int ni = 0; ni < 4; ni++)
                    mmah(acc[mi][ni], a[mi], bb[ni]);
        }

        #pragma unroll
        for (int mi = 0; mi < 2; mi++) {
            #pragma unroll
            for (int ni = 0; ni < 4; ni++) {
                #pragma unroll
                for (int ep = 0; ep < 2; ep++) {
                    int row = cb + wr0 + mi*16 + g + ep*8;
                    int col = n0 + wc0 + ni*8 + 2*q;
                    size_t o = ((size_t)b*C_ + row) * N_ + col;
                    float wb = Wb[row];
                    float2 xv = *reinterpret_cast<const float2*>(x + o);
                    float2 ov;
                    ov.x = acc[mi][ni][ep*2    ] + wb + xv.x;
                    ov.y = acc[mi][ni][ep*2 + 1] + wb + xv.y;
                    *reinterpret_cast<float2*>(out + o) = ov;
                }
            }
        }
    }
}

// =====================================================================
extern "C" void kernel_launch(void* const* d_in, const int* in_sizes, int n_in,
                              void* d_out, int out_size)
{
    const float* x    = (const float*)d_in[0];
    const float* g_w  = (const float*)d_in[1];
    const float* g_b  = (const float*)d_in[2];
    const float* th_w = (const float*)d_in[3];
    const float* th_b = (const float*)d_in[4];
    const float* ph_w = (const float*)d_in[5];
    const float* ph_b = (const float*)d_in[6];
    const float* Ww   = (const float*)d_in[7];
    const float* Wb   = (const float*)d_in[8];
    float* out = (float*)d_out;

    const int SM1 = 87040;
    const int SM2 = 111104;
    const int SM3 = 110592;

    cudaFuncSetAttribute(k1_proj,  cudaFuncAttributeMaxDynamicSharedMemorySize, SM1);
    cudaFuncSetAttribute(k2_stats, cudaFuncAttributeMaxDynamicSharedMemorySize, SM2);
    cudaFuncSetAttribute(k3_attn,  cudaFuncAttributeMaxDynamicSharedMemorySize, SM3);

    k1_proj <<<dim3(256),    256, SM1>>>(x, g_w, g_b, th_w, th_b, ph_w, ph_b);
    k2_stats<<<dim3(32, 8),  256, SM2>>>();
    k3_attn <<<dim3(32, 8),  256, SM3>>>(x, Ww, Wb, out);
}